// round 14
// baseline (speedup 1.0000x reference)
#include <cuda_runtime.h>
#include <cuda_bf16.h>
#include <math.h>

#define NN 262144
#define CC 256

// ---- gmem scratch (__device__ globals per allocation rules) ----
__device__ unsigned       g_qpk[(size_t)NN * CC];    // q packed (hi,lo bf16) [N][C]
__device__ unsigned short g_xh [(size_t)NN * CC];    // x split
__device__ unsigned short g_xl [(size_t)NN * CC];
__device__ unsigned short g_wh [3 * CC * CC];        // Wq,Wk,Wv split
__device__ unsigned short g_wl [3 * CC * CC];
__device__ unsigned short g_kth[(size_t)CC * NN];    // k^T split [C][N]
__device__ unsigned short g_ktl[(size_t)CC * NN];
__device__ unsigned short g_vth[(size_t)CC * NN];    // v^T split [C][N]
__device__ unsigned short g_vtl[(size_t)CC * NN];
__device__ unsigned short g_mth[CC * CC];            // Mt split [j][c]
__device__ unsigned short g_mtl[CC * CC];
__device__ float g_kv[CC * CC];
__device__ float g_ksum[CC];

// ---- smem: 3 stages of 4 compact planes (128 rows x 32 bf16 = 64B rows, XOR swizzle)
#define PAH  0
#define PAL  8192
#define PBH  16384
#define PBL  24576
#define SS   32768                  // bytes per stage
#define SMEM_DYN (3*SS + 3072)      // + bo/ks/z tail for out_mma

// ------------------------- helpers -------------------------
__device__ __forceinline__ unsigned smem_u32(const void* p){
    unsigned a;
    asm("{ .reg .u64 t; cvta.to.shared.u64 t, %1; cvt.u32.u64 %0, t; }":"=r"(a):"l"(p));
    return a;
}
__device__ __forceinline__ unsigned fsplit(float f){
    __nv_bfloat16 h = __float2bfloat16(f);
    __nv_bfloat16 l = __float2bfloat16(f - __bfloat162float(h));
    return (unsigned)__bfloat16_as_ushort(h) | ((unsigned)__bfloat16_as_ushort(l) << 16);
}
__device__ __forceinline__ float pkval(unsigned p){
    return __bfloat162float(__ushort_as_bfloat16((unsigned short)(p & 0xffffu)))
         + __bfloat162float(__ushort_as_bfloat16((unsigned short)(p >> 16)));
}
__device__ __forceinline__ void cpa16(unsigned d, const void* s){
    asm volatile("cp.async.cg.shared.global [%0], [%1], 16;" :: "r"(d), "l"(s));
}
__device__ __forceinline__ void cpcommit(){ asm volatile("cp.async.commit_group;" ::: "memory"); }
template<int N>
__device__ __forceinline__ void cpwaitg(){ asm volatile("cp.async.wait_group %0;" :: "n"(N) : "memory"); }

// swizzled byte offset of 16B chunk (row, chunk) inside a 128x64B plane
// s(row) = (row&3) ^ ((row>>2)&1); invariant under row += 16.
__device__ __forceinline__ unsigned swoff(int row, int chunk, int s){
    return (unsigned)(row*64 + ((chunk ^ s) << 4));
}
__device__ __forceinline__ void ldsm4(unsigned* r, unsigned addr){
    asm volatile("ldmatrix.sync.aligned.m8n8.x4.shared.b16 {%0,%1,%2,%3}, [%4];"
        : "=r"(r[0]),"=r"(r[1]),"=r"(r[2]),"=r"(r[3]) : "r"(addr));
}
// non-volatile: pure register semantics; lets ptxas interleave MMA with LDSM
__device__ __forceinline__ void mma16816(float* c, const unsigned* a, const unsigned* b){
    asm("mma.sync.aligned.m16n8k16.row.col.f32.bf16.bf16.f32 "
        "{%0,%1,%2,%3},{%4,%5,%6,%7},{%8,%9},{%0,%1,%2,%3};"
        : "+f"(c[0]),"+f"(c[1]),"+f"(c[2]),"+f"(c[3])
        : "r"(a[0]),"r"(a[1]),"r"(a[2]),"r"(a[3]), "r"(b[0]),"r"(b[1]));
}
// one K=32 chunk: 2 k16 steps x 3 split terms over 64x64 warp tile (4 warps/CTA).
// 32 ldsm / 192 MMA per warp-chunk: 33% less smem traffic per MMA than 32x64 tiles.
__device__ __forceinline__ void chunk_mma64(unsigned sbase, int wm, int wn, int lane, int sw,
                                            float acc[4][8][4]){
    const int arow = wm*64 + (lane & 15);
    const int akb  = (lane >> 4) & 1;
    const int brow = wn*64 + (lane & 7) + ((lane & 16) >> 1);
    const int bkb  = (lane >> 3) & 1;
#pragma unroll
    for (int s = 0; s < 2; ++s){
        const unsigned ca = (unsigned)((((s << 1) | akb) ^ sw) << 4);
        const unsigned cb = (unsigned)((((s << 1) | bkb) ^ sw) << 4);
        unsigned ah[4][4], al[4][4];
#pragma unroll
        for (int t = 0; t < 4; ++t){
            unsigned base = sbase + (unsigned)((arow + 16*t)*64) + ca;
            ldsm4(ah[t], base + PAH);
            ldsm4(al[t], base + PAL);
        }
#pragma unroll
        for (int nb = 0; nb < 2; ++nb){
            unsigned bh[4][2], bl[4][2];
#pragma unroll
            for (int u = 0; u < 2; ++u){
                unsigned base = sbase + (unsigned)((brow + nb*32 + 16*u)*64) + cb;
                unsigned r[4];
                ldsm4(r, base + PBH);
                bh[2*u][0]=r[0]; bh[2*u][1]=r[1]; bh[2*u+1][0]=r[2]; bh[2*u+1][1]=r[3];
                ldsm4(r, base + PBL);
                bl[2*u][0]=r[0]; bl[2*u][1]=r[1]; bl[2*u+1][0]=r[2]; bl[2*u+1][1]=r[3];
            }
#pragma unroll
            for (int t = 0; t < 4; ++t)
#pragma unroll
                for (int u = 0; u < 4; ++u) mma16816(acc[t][nb*4+u], ah[t], bh[u]);
#pragma unroll
            for (int t = 0; t < 4; ++t)
#pragma unroll
                for (int u = 0; u < 4; ++u) mma16816(acc[t][nb*4+u], ah[t], bl[u]);
#pragma unroll
            for (int t = 0; t < 4; ++t)
#pragma unroll
                for (int u = 0; u < 4; ++u) mma16816(acc[t][nb*4+u], al[t], bh[u]);
        }
    }
}
__device__ __forceinline__ float elu1(float f){ return (f > 0.f) ? f + 1.f : expf(f); }

// ------------------------- presplit x and W -------------------------
__global__ void __launch_bounds__(256) presplit_x(const float* __restrict__ x)
{
    size_t i = ((size_t)blockIdx.x * 256 + threadIdx.x) * 8;
#pragma unroll
    for (int g = 0; g < 2; ++g){
        float4 v = *(const float4*)(x + i + g*4);
        unsigned p0 = fsplit(v.x), p1 = fsplit(v.y), p2 = fsplit(v.z), p3 = fsplit(v.w);
        uint2 h, l;
        h.x = (p0&0xffffu)|(p1<<16); h.y = (p2&0xffffu)|(p3<<16);
        l.x = (p0>>16)|(p1&0xffff0000u); l.y = (p2>>16)|(p3&0xffff0000u);
        *(uint2*)(g_xh + i + g*4) = h;
        *(uint2*)(g_xl + i + g*4) = l;
    }
}
__global__ void __launch_bounds__(256)
presplit_w(const float* __restrict__ Wq, const float* __restrict__ Wk,
           const float* __restrict__ Wv)
{
    int idx = blockIdx.x * 256 + threadIdx.x;
    int w = idx >> 14;
    size_t off = (size_t)w * 65536 + (size_t)(idx & 16383) * 4;
    const float* W = (w == 0) ? Wq : (w == 1) ? Wk : Wv;
    float4 v = *(const float4*)(W + (size_t)(idx & 16383) * 4);
    unsigned p0 = fsplit(v.x), p1 = fsplit(v.y), p2 = fsplit(v.z), p3 = fsplit(v.w);
    uint2 h, l;
    h.x = (p0&0xffffu)|(p1<<16); h.y = (p2&0xffffu)|(p3<<16);
    l.x = (p0>>16)|(p1&0xffff0000u); l.y = (p2>>16)|(p3&0xffff0000u);
    *(uint2*)(g_wh + off) = h;
    *(uint2*)(g_wl + off) = l;
}

__global__ void zero_kernel()
{
    int i = blockIdx.x * blockDim.x + threadIdx.x;
    if (i < CC*CC) g_kv[i] = 0.f;
    if (i < CC) g_ksum[i] = 0.f;
}

// ------------------------- qkv projections (64x64 tiles, 3-stage ring) --------------------
__global__ void __launch_bounds__(128, 2)
qkv_mma()
{
    extern __shared__ __align__(128) unsigned char sm[];
    const unsigned sb = smem_u32(sm);
    unsigned* sm32 = (unsigned*)(sm + SS);           // transpose scratch in buf1/buf2
    const int tid = threadIdx.x, lane = tid & 31, wid = tid >> 5;   // 4 warps
    const int wm = wid >> 1, wn = wid & 1;
    const int r0 = blockIdx.x << 7;
    const int sws = ((tid & 3) ^ ((tid >> 2) & 1));  // store-side swizzle (row = tid)
    const int sw  = ((lane & 3) ^ ((lane >> 2) & 1)); // load-side swizzle

    auto issue = [&](int w, int nh, int c, int buf){
        const size_t oa = (size_t)(r0 + tid)*CC + c*32;
        const size_t ob = (size_t)w*65536 + (size_t)(nh*128 + tid)*CC + c*32;
        const unsigned d = sb + (unsigned)(buf*SS);
#pragma unroll
        for (int ch = 0; ch < 4; ++ch){
            const unsigned o = swoff(tid, ch, sws);
            cpa16(d + PAH + o, g_xh + oa + ch*8);
            cpa16(d + PAL + o, g_xl + oa + ch*8);
            cpa16(d + PBH + o, g_wh + ob + ch*8);
            cpa16(d + PBL + o, g_wl + ob + ch*8);
        }
        cpcommit();
    };

    issue(0, 0, 0, 0);   // pass 0, chunk 0
    for (int pass = 0; pass < 6; ++pass){
        const int w = pass >> 1, nh = pass & 1;
        float acc[4][8][4];
#pragma unroll
        for (int t = 0; t < 4; ++t)
#pragma unroll
            for (int u = 0; u < 8; ++u)
#pragma unroll
                for (int e = 0; e < 4; ++e) acc[t][u][e] = 0.f;

        for (int c = 0; c < 8; ++c){
            if (c < 7){
                issue(w, nh, c + 1, (c + 1) % 3);
                cpwaitg<1>();
                __syncthreads();
            } else {
                cpwaitg<0>();
                __syncthreads();      // ALL warps done chunk_mma(6) -> buf0 free
                if (pass < 5){
                    const int np = pass + 1;   // prefetch next pass chunk 0 into buf0
                    issue(np >> 1, np & 1, 0, 0);
                }
            }
            chunk_mma64(sb + (unsigned)((c % 3)*SS), wm, wn, lane, sw, acc);
        }

        if (w == 0){
#pragma unroll
            for (int t = 0; t < 4; ++t){
                const int m = wm*64 + 16*t + (lane >> 2);
#pragma unroll
                for (int u = 0; u < 8; ++u){
                    const int ng = nh*128 + wn*64 + u*8 + 2*(lane & 3);
                    uint2 o;
                    o.x = fsplit(elu1(acc[t][u][0]));
                    o.y = fsplit(elu1(acc[t][u][1]));
                    *(uint2*)(g_qpk + (size_t)(r0 + m)*CC + ng) = o;
                    o.x = fsplit(elu1(acc[t][u][2]));
                    o.y = fsplit(elu1(acc[t][u][3]));
                    *(uint2*)(g_qpk + (size_t)(r0 + m + 8)*CC + ng) = o;
                }
            }
            __syncthreads();   // chunk_mma(7) (buf1 readers) done before next pass issues buf1
        } else {
            unsigned short* Gh = (w == 1) ? g_kth : g_vth;
            unsigned short* Gl = (w == 1) ? g_ktl : g_vtl;
            for (int h4 = 0; h4 < 2; ++h4){
                __syncthreads();    // chunk_mma(7) done CTA-wide -> buf1/buf2 scratch free
                if (wn == h4){      // 2 warps (wm=0,1) write 128 rows x 64 cols
#pragma unroll
                    for (int t = 0; t < 4; ++t){
                        const int m = wm*64 + 16*t + (lane >> 2);
#pragma unroll
                        for (int u = 0; u < 8; ++u){
                            const int nl = u*8 + 2*(lane & 3);
                            float f0 = acc[t][u][0], f1 = acc[t][u][1];
                            float f2 = acc[t][u][2], f3 = acc[t][u][3];
                            if (w == 1){ f0=elu1(f0); f1=elu1(f1); f2=elu1(f2); f3=elu1(f3); }
                            sm32[(m    )*65 + nl    ] = fsplit(f0);
                            sm32[(m    )*65 + nl + 1] = fsplit(f1);
                            sm32[(m + 8)*65 + nl    ] = fsplit(f2);
                            sm32[(m + 8)*65 + nl + 1] = fsplit(f3);
                        }
                    }
                }
                __syncthreads();
#pragma unroll
                for (int j = 0; j < 16; ++j){
                    const int np = wid + 4*j;           // 0..63
                    const int ng = nh*128 + h4*64 + np;
                    float ks = 0.f;
#pragma unroll
                    for (int i = 0; i < 4; ++i){
                        unsigned p = sm32[(i*32 + lane)*65 + np];
                        Gh[(size_t)ng*NN + r0 + i*32 + lane] = (unsigned short)(p & 0xffffu);
                        Gl[(size_t)ng*NN + r0 + i*32 + lane] = (unsigned short)(p >> 16);
                        if (w == 1) ks += pkval(p);
                    }
                    if (w == 1){
#pragma unroll
                        for (int o = 16; o; o >>= 1) ks += __shfl_xor_sync(0xFFFFFFFFu, ks, o);
                        if (!lane) atomicAdd(&g_ksum[ng], ks);
                    }
                }
            }
            __syncthreads();   // scratch readers done before next pass issues buf1
        }
    }
}

// ------------------------- kv = k^T v, split-K (64x64 tiles, full wave) -------------------
__global__ void __launch_bounds__(128, 2) kv_mma()
{
    extern __shared__ __align__(128) unsigned char sm[];
    const unsigned sb = smem_u32(sm);
    const int tid = threadIdx.x, lane = tid & 31, wid = tid >> 5;
    const int wm = wid >> 1, wn = wid & 1;
    const int a0 = blockIdx.x << 7, b0 = blockIdx.y << 7;
    // 74 z-slices: 73 x 3584 rows (112 chunks) + 1 x 512 rows (16 chunks) = 262144
    const int NCH = (blockIdx.z < 73) ? 112 : 16;
    const size_t i0 = (size_t)blockIdx.z * 3584;
    const int sws = ((tid & 3) ^ ((tid >> 2) & 1));
    const int sw  = ((lane & 3) ^ ((lane >> 2) & 1));

    float acc[4][8][4];
#pragma unroll
    for (int t = 0; t < 4; ++t)
#pragma unroll
        for (int u = 0; u < 8; ++u)
#pragma unroll
            for (int e = 0; e < 4; ++e) acc[t][u][e] = 0.f;

    auto issue = [&](int c, int buf){
        const size_t oa = (size_t)(a0 + tid)*NN + i0 + c*32;
        const size_t ob = (size_t)(b0 + tid)*NN + i0 + c*32;
        const unsigned d = sb + (unsigned)(buf*SS);
#pragma unroll
        for (int ch = 0; ch < 4; ++ch){
            const unsigned o = swoff(tid, ch, sws);
            cpa16(d + PAH + o, g_kth + oa + ch*8);
            cpa16(d + PAL + o, g_ktl + oa + ch*8);
            cpa16(d + PBH + o, g_vth + ob + ch*8);
            cpa16(d + PBL + o, g_vtl + ob + ch*8);
        }
        cpcommit();
    };
    issue(0, 0);
    for (int c = 0; c < NCH; ++c){
        if (c < NCH - 1){ issue(c + 1, (c + 1) % 3); cpwaitg<1>(); }
        else cpwaitg<0>();
        __syncthreads();
        chunk_mma64(sb + (unsigned)((c % 3)*SS), wm, wn, lane, sw, acc);
    }
#pragma unroll
    for (int t = 0; t < 4; ++t){
        const int m = wm*64 + 16*t + (lane >> 2);
#pragma unroll
        for (int u = 0; u < 8; ++u){
            const int n = wn*64 + u*8 + 2*(lane & 3);
            atomicAdd(&g_kv[(a0 + m    )*CC + b0 + n    ], acc[t][u][0]);
            atomicAdd(&g_kv[(a0 + m    )*CC + b0 + n + 1], acc[t][u][1]);
            atomicAdd(&g_kv[(a0 + m + 8)*CC + b0 + n    ], acc[t][u][2]);
            atomicAdd(&g_kv[(a0 + m + 8)*CC + b0 + n + 1], acc[t][u][3]);
        }
    }
}

// ------------------------- Mt[j][a] = sum_b kv[a][b] Wo[j][b], split store ---------------
__global__ void __launch_bounds__(256) m_kernel(const float* __restrict__ Wo)
{
    __shared__ float wo_s[256];
    const int j = blockIdx.x, a = threadIdx.x;
    wo_s[a] = Wo[(size_t)j*CC + a];
    __syncthreads();
    const float* kvr = g_kv + (size_t)a*CC;
    float s = 0.f;
#pragma unroll 8
    for (int b = 0; b < CC; ++b) s += kvr[b] * wo_s[b];
    unsigned p = fsplit(s);
    g_mth[j*CC + a] = (unsigned short)(p & 0xffffu);
    g_mtl[j*CC + a] = (unsigned short)(p >> 16);
}

// ------------------------- out = z * (q @ Mt^T) + bo  (64x64 tiles, z fused) --------------
__global__ void __launch_bounds__(128, 2)
out_mma(const float* __restrict__ bo, float* __restrict__ out)
{
    extern __shared__ __align__(128) unsigned char sm[];
    const unsigned sb = smem_u32(sm);
    float* bo_s = (float*)(sm + 3*SS);
    float* ks_s = bo_s + 256;
    float* z_s  = ks_s + 256;
    const int tid = threadIdx.x, lane = tid & 31, wid = tid >> 5;
    const int wm = wid >> 1, wn = wid & 1;
    const int r0 = blockIdx.x << 7;
    const int sws = ((tid & 3) ^ ((tid >> 2) & 1));
    const int sw  = ((lane & 3) ^ ((lane >> 2) & 1));
    bo_s[tid] = bo[tid]; bo_s[tid + 128] = bo[tid + 128];
    ks_s[tid] = g_ksum[tid]; ks_s[tid + 128] = g_ksum[tid + 128];
    __syncthreads();

    auto issueB = [&](int nh, int c, int buf){
        const size_t ob = (size_t)(nh*128 + tid)*CC + c*32;
        const unsigned d = sb + (unsigned)(buf*SS);
#pragma unroll
        for (int ch = 0; ch < 4; ++ch){
            const unsigned o = swoff(tid, ch, sws);
            cpa16(d + PBH + o, g_mth + ob + ch*8);
            cpa16(d + PBL + o, g_mtl + ob + ch*8);
        }
        cpcommit();
    };

    float zacc = 0.f;
    issueB(0, 0, 0);
    for (int nh = 0; nh < 2; ++nh){
        float acc[4][8][4];
#pragma unroll
        for (int t = 0; t < 4; ++t)
#pragma unroll
            for (int u = 0; u < 8; ++u)
#pragma unroll
                for (int e = 0; e < 4; ++e) acc[t][u][e] = 0.f;

        for (int c = 0; c < 8; ++c){
            // A register staging into buf c%3 PAH/PAL (+ fused z on nh==0); safe:
            // that buffer's PAH/PAL last readers (chunk c-3) finished before B(c-1).
            {
                unsigned char* smb = sm + (c % 3)*SS;
                const unsigned* qs = g_qpk + (size_t)(r0 + tid)*CC + c*32;
#pragma unroll
                for (int ch = 0; ch < 4; ++ch){
                    uint2 A = *(const uint2*)(qs + ch*8);
                    uint2 B = *(const uint2*)(qs + ch*8 + 2);
                    uint2 Cq = *(const uint2*)(qs + ch*8 + 4);
                    uint2 D = *(const uint2*)(qs + ch*8 + 6);
                    unsigned p[8] = {A.x,A.y,B.x,B.y,Cq.x,Cq.y,D.x,D.y};
                    uint4 h, l;
                    h.x=(p[0]&0xffffu)|(p[1]<<16); h.y=(p[2]&0xffffu)|(p[3]<<16);
                    h.z=(p[4]&0xffffu)|(p[5]<<16); h.w=(p[6]&0xffffu)|(p[7]<<16);
                    l.x=(p[0]>>16)|(p[1]&0xffff0000u); l.y=(p[2]>>16)|(p[3]&0xffff0000u);
                    l.z=(p[4]>>16)|(p[5]&0xffff0000u); l.w=(p[6]>>16)|(p[7]&0xffff0000u);
                    const unsigned og = swoff(tid, ch, sws);
                    *(uint4*)(smb + PAH + og) = h;
                    *(uint4*)(smb + PAL + og) = l;
                    if (nh == 0){
                        const float* kp = ks_s + c*32 + ch*8;
#pragma unroll
                        for (int u2 = 0; u2 < 8; ++u2) zacc += pkval(p[u2]) * kp[u2];
                    }
                }
            }
            if (c < 7){
                issueB(nh, c + 1, (c + 1) % 3);
                cpwaitg<1>();
                __syncthreads();
            } else {
                cpwaitg<0>();
                __syncthreads();      // ALL warps done chunk_mma(6) -> buf0 free
                if (nh == 0) issueB(1, 0, 0);   // prefetch nh=1 chunk0 into buf0
            }
            chunk_mma64(sb + (unsigned)((c % 3)*SS), wm, wn, lane, sw, acc);
        }
        if (nh == 0) z_s[tid] = 1.f / fmaxf(zacc, 1e-6f);   // row tid fully owned by thread
        __syncthreads();   // z_s visible; all chunk_mma(7) done before nh=1 stages buf0 PAH

#pragma unroll
        for (int t = 0; t < 4; ++t){
            const int m = wm*64 + 16*t + (lane >> 2);
            const float z0 = z_s[m], z1 = z_s[m + 8];
#pragma unroll
            for (int u = 0; u < 8; ++u){
                const int ng = nh*128 + wn*64 + u*8 + 2*(lane & 3);
                float2 o;
                o.x = acc[t][u][0]*z0 + bo_s[ng];
                o.y = acc[t][u][1]*z0 + bo_s[ng + 1];
                *(float2*)(out + (size_t)(r0 + m)*CC + ng) = o;
                o.x = acc[t][u][2]*z1 + bo_s[ng];
                o.y = acc[t][u][3]*z1 + bo_s[ng + 1];
                *(float2*)(out + (size_t)(r0 + m + 8)*CC + ng) = o;
            }
        }
    }
}

// ------------------------- launch -------------------------
extern "C" void kernel_launch(void* const* d_in, const int* in_sizes, int n_in,
                              void* d_out, int out_size)
{
    (void)in_sizes; (void)n_in; (void)out_size;
    const float* x  = (const float*)d_in[0];
    const float* Wq = (const float*)d_in[1];
    const float* Wk = (const float*)d_in[2];
    const float* Wv = (const float*)d_in[3];
    const float* Wo = (const float*)d_in[4];
    const float* bo = (const float*)d_in[5];
    float* out = (float*)d_out;

    static int inited = 0;
    if (!inited){
        cudaFuncSetAttribute(qkv_mma, cudaFuncAttributeMaxDynamicSharedMemorySize, SMEM_DYN);
        cudaFuncSetAttribute(kv_mma,  cudaFuncAttributeMaxDynamicSharedMemorySize, SMEM_DYN);
        cudaFuncSetAttribute(out_mma, cudaFuncAttributeMaxDynamicSharedMemorySize, SMEM_DYN);
        inited = 1;
    }

    zero_kernel<<<256, 256>>>();
    presplit_x<<<32768, 256>>>(x);
    presplit_w<<<192, 256>>>(Wq, Wk, Wv);
    qkv_mma<<<NN/128, 128, SMEM_DYN>>>();
    kv_mma<<<dim3(2, 2, 74), 128, SMEM_DYN>>>();
    m_kernel<<<256, 256>>>(Wo);
    out_mma<<<NN/128, 128, SMEM_DYN>>>(bo, out);
}

// round 15
// speedup vs baseline: 1.4523x; 1.4523x over previous
#include <cuda_runtime.h>
#include <cuda_bf16.h>
#include <math.h>

#define NN 262144
#define CC 256

// ---- gmem scratch (__device__ globals per allocation rules) ----
__device__ unsigned       g_qpk[(size_t)NN * CC];    // q packed (hi,lo bf16) [N][C]
__device__ unsigned short g_wh [3 * CC * CC];        // Wq,Wk,Wv split
__device__ unsigned short g_wl [3 * CC * CC];
__device__ unsigned short g_kth[(size_t)CC * NN];    // k^T split [C][N]
__device__ unsigned short g_ktl[(size_t)CC * NN];
__device__ unsigned short g_vth[(size_t)CC * NN];    // v^T split [C][N]
__device__ unsigned short g_vtl[(size_t)CC * NN];
__device__ unsigned short g_mth[CC * CC];            // Mt split [j][c]
__device__ unsigned short g_mtl[CC * CC];
__device__ float g_kv[CC * CC];
__device__ float g_ksum[CC];

// ---- smem: 3 stages of 4 compact planes (128 rows x 32 bf16 = 64B rows, XOR swizzle)
#define PAH  0
#define PAL  8192
#define PBH  16384
#define PBL  24576
#define SS   32768                  // bytes per stage
#define SMEM_DYN (3*SS + 3072)      // + bo/ks/z tail for out_mma

// ------------------------- helpers -------------------------
__device__ __forceinline__ unsigned smem_u32(const void* p){
    unsigned a;
    asm("{ .reg .u64 t; cvta.to.shared.u64 t, %1; cvt.u32.u64 %0, t; }":"=r"(a):"l"(p));
    return a;
}
__device__ __forceinline__ unsigned fsplit(float f){
    __nv_bfloat16 h = __float2bfloat16(f);
    __nv_bfloat16 l = __float2bfloat16(f - __bfloat162float(h));
    return (unsigned)__bfloat16_as_ushort(h) | ((unsigned)__bfloat16_as_ushort(l) << 16);
}
__device__ __forceinline__ float pkval(unsigned p){
    return __bfloat162float(__ushort_as_bfloat16((unsigned short)(p & 0xffffu)))
         + __bfloat162float(__ushort_as_bfloat16((unsigned short)(p >> 16)));
}
__device__ __forceinline__ void cpa16(unsigned d, const void* s){
    asm volatile("cp.async.cg.shared.global [%0], [%1], 16;" :: "r"(d), "l"(s));
}
__device__ __forceinline__ void cpcommit(){ asm volatile("cp.async.commit_group;" ::: "memory"); }
template<int N>
__device__ __forceinline__ void cpwaitg(){ asm volatile("cp.async.wait_group %0;" :: "n"(N) : "memory"); }

// swizzled byte offset of 16B chunk (row, chunk) inside a 128x64B plane
// s(row) = (row&3) ^ ((row>>2)&1); invariant under row += 16.
__device__ __forceinline__ unsigned swoff(int row, int chunk, int s){
    return (unsigned)(row*64 + ((chunk ^ s) << 4));
}
__device__ __forceinline__ void ldsm4(unsigned* r, unsigned addr){
    asm volatile("ldmatrix.sync.aligned.m8n8.x4.shared.b16 {%0,%1,%2,%3}, [%4];"
        : "=r"(r[0]),"=r"(r[1]),"=r"(r[2]),"=r"(r[3]) : "r"(addr));
}
// non-volatile: pure register semantics; lets ptxas interleave MMA with LDSM
__device__ __forceinline__ void mma16816(float* c, const unsigned* a, const unsigned* b){
    asm("mma.sync.aligned.m16n8k16.row.col.f32.bf16.bf16.f32 "
        "{%0,%1,%2,%3},{%4,%5,%6,%7},{%8,%9},{%0,%1,%2,%3};"
        : "+f"(c[0]),"+f"(c[1]),"+f"(c[2]),"+f"(c[3])
        : "r"(a[0]),"r"(a[1]),"r"(a[2]),"r"(a[3]), "r"(b[0]),"r"(b[1]));
}
// one K=32 chunk: 2 k16 steps x 3 split terms over warp tile 32x64.
__device__ __forceinline__ void chunk_mma(unsigned sbase, int wm, int wn, int lane, int sw,
                                          float acc[2][8][4]){
    const int arow = wm*32 + (lane & 15);
    const int akb  = (lane >> 4) & 1;
    const int brow = wn*64 + (lane & 7) + ((lane & 16) >> 1);
    const int bkb  = (lane >> 3) & 1;
#pragma unroll
    for (int s = 0; s < 2; ++s){
        const unsigned ca = (unsigned)((((s << 1) | akb) ^ sw) << 4);
        const unsigned cb = (unsigned)((((s << 1) | bkb) ^ sw) << 4);
        unsigned ah[2][4], al[2][4], bh[8][2], bl[8][2];
#pragma unroll
        for (int t = 0; t < 2; ++t){
            unsigned base = sbase + (unsigned)((arow + 16*t)*64) + ca;
            ldsm4(ah[t], base + PAH);
            ldsm4(al[t], base + PAL);
        }
#pragma unroll
        for (int u = 0; u < 4; ++u){
            unsigned base = sbase + (unsigned)((brow + 16*u)*64) + cb;
            unsigned r[4];
            ldsm4(r, base + PBH);
            bh[2*u][0]=r[0]; bh[2*u][1]=r[1]; bh[2*u+1][0]=r[2]; bh[2*u+1][1]=r[3];
            ldsm4(r, base + PBL);
            bl[2*u][0]=r[0]; bl[2*u][1]=r[1]; bl[2*u+1][0]=r[2]; bl[2*u+1][1]=r[3];
        }
#pragma unroll
        for (int t = 0; t < 2; ++t)
#pragma unroll
            for (int u = 0; u < 8; ++u) mma16816(acc[t][u], ah[t], bh[u]);
#pragma unroll
        for (int t = 0; t < 2; ++t)
#pragma unroll
            for (int u = 0; u < 8; ++u) mma16816(acc[t][u], ah[t], bl[u]);
#pragma unroll
        for (int t = 0; t < 2; ++t)
#pragma unroll
            for (int u = 0; u < 8; ++u) mma16816(acc[t][u], al[t], bh[u]);
    }
}
__device__ __forceinline__ float elu1(float f){ return (f > 0.f) ? f + 1.f : expf(f); }

// ------------------------- presplit W (tiny) -------------------------
__global__ void __launch_bounds__(256)
presplit_w(const float* __restrict__ Wq, const float* __restrict__ Wk,
           const float* __restrict__ Wv)
{
    int idx = blockIdx.x * 256 + threadIdx.x;
    int w = idx >> 14;
    size_t off = (size_t)w * 65536 + (size_t)(idx & 16383) * 4;
    const float* W = (w == 0) ? Wq : (w == 1) ? Wk : Wv;
    float4 v = *(const float4*)(W + (size_t)(idx & 16383) * 4);
    unsigned p0 = fsplit(v.x), p1 = fsplit(v.y), p2 = fsplit(v.z), p3 = fsplit(v.w);
    uint2 h, l;
    h.x = (p0&0xffffu)|(p1<<16); h.y = (p2&0xffffu)|(p3<<16);
    l.x = (p0>>16)|(p1&0xffff0000u); l.y = (p2>>16)|(p3&0xffff0000u);
    *(uint2*)(g_wh + off) = h;
    *(uint2*)(g_wl + off) = l;
}

__global__ void zero_kernel()
{
    int i = blockIdx.x * blockDim.x + threadIdx.x;
    if (i < CC*CC) g_kv[i] = 0.f;
    if (i < CC) g_ksum[i] = 0.f;
}

// ------------------------- qkv projections (A register-split from x, B cp.async) ----------
__global__ void __launch_bounds__(256, 2)
qkv_mma(const float* __restrict__ x)
{
    extern __shared__ __align__(128) unsigned char sm[];
    const unsigned sb = smem_u32(sm);
    unsigned* sm32 = (unsigned*)(sm + SS);           // transpose scratch in buf1/buf2
    const int tid = threadIdx.x, lane = tid & 31, wid = tid >> 5;
    const int wm = wid >> 1, wn = wid & 1;
    const int r0 = blockIdx.x << 7;
    const int row = tid >> 1, e0 = (tid & 1) << 4;   // staged elems [e0, e0+16)
    const int c0 = (tid & 1) << 1;                   // first 16B chunk
    const int sws = ((row & 3) ^ ((row >> 2) & 1));  // store-side swizzle
    const int sw  = ((lane & 3) ^ ((lane >> 2) & 1)); // load-side swizzle
    const unsigned o1 = swoff(row, c0, sws), o2 = swoff(row, c0 + 1, sws);

    // B-only cp.async issue
    auto issueB = [&](int w, int nh, int c, int buf){
        const size_t ob = (size_t)w*65536 + (size_t)(nh*128 + row)*CC + c*32 + e0;
        const unsigned d = sb + (unsigned)(buf*SS);
        cpa16(d + PBH + o1, g_wh + ob); cpa16(d + PBH + o2, g_wh + ob + 8);
        cpa16(d + PBL + o1, g_wl + ob); cpa16(d + PBL + o2, g_wl + ob + 8);
        cpcommit();
    };
    // A register staging: fp32 x -> fsplit -> hi/lo planes of buf
    auto stageA = [&](int c, int buf){
        unsigned char* smb = sm + buf*SS;
        const float* xs = x + (size_t)(r0 + row)*CC + c*32 + e0;
#pragma unroll
        for (int g = 0; g < 2; ++g){
            float4 a = *(const float4*)(xs + g*8);
            float4 b = *(const float4*)(xs + g*8 + 4);
            unsigned p[8] = {fsplit(a.x),fsplit(a.y),fsplit(a.z),fsplit(a.w),
                             fsplit(b.x),fsplit(b.y),fsplit(b.z),fsplit(b.w)};
            uint4 h, l;
            h.x=(p[0]&0xffffu)|(p[1]<<16); h.y=(p[2]&0xffffu)|(p[3]<<16);
            h.z=(p[4]&0xffffu)|(p[5]<<16); h.w=(p[6]&0xffffu)|(p[7]<<16);
            l.x=(p[0]>>16)|(p[1]&0xffff0000u); l.y=(p[2]>>16)|(p[3]&0xffff0000u);
            l.z=(p[4]>>16)|(p[5]&0xffff0000u); l.w=(p[6]>>16)|(p[7]&0xffff0000u);
            const unsigned og = swoff(row, c0 + g, sws);
            *(uint4*)(smb + PAH + og) = h;
            *(uint4*)(smb + PAL + og) = l;
        }
    };

    issueB(0, 0, 0, 0);   // pass 0, chunk 0 (B)
    for (int pass = 0; pass < 6; ++pass){
        const int w = pass >> 1, nh = pass & 1;
        float acc[2][8][4];
#pragma unroll
        for (int t = 0; t < 2; ++t)
#pragma unroll
            for (int u = 0; u < 8; ++u)
#pragma unroll
                for (int e = 0; e < 4; ++e) acc[t][u][e] = 0.f;

        for (int c = 0; c < 8; ++c){
            // stage A into buf c%3 (safe: PAH/PAL last readers = chunk c-3, done
            // before barrier B(c-2); for c<3, buffer free since previous pass epilogue)
            stageA(c, c % 3);
            if (c < 7){
                issueB(w, nh, c + 1, (c + 1) % 3);
                cpwaitg<1>();
                __syncthreads();
            } else {
                cpwaitg<0>();
                __syncthreads();      // ALL warps done chunk_mma(6) -> buf0 free
                if (pass < 5){
                    const int np = pass + 1;   // prefetch next pass chunk 0 B into buf0
                    issueB(np >> 1, np & 1, 0, 0);
                }
            }
            chunk_mma(sb + (unsigned)((c % 3)*SS), wm, wn, lane, sw, acc);
        }

        if (w == 0){
#pragma unroll
            for (int t = 0; t < 2; ++t){
                const int m = wm*32 + 16*t + (lane >> 2);
#pragma unroll
                for (int u = 0; u < 8; ++u){
                    const int ng = nh*128 + wn*64 + u*8 + 2*(lane & 3);
                    uint2 o;
                    o.x = fsplit(elu1(acc[t][u][0]));
                    o.y = fsplit(elu1(acc[t][u][1]));
                    *(uint2*)(g_qpk + (size_t)(r0 + m)*CC + ng) = o;
                    o.x = fsplit(elu1(acc[t][u][2]));
                    o.y = fsplit(elu1(acc[t][u][3]));
                    *(uint2*)(g_qpk + (size_t)(r0 + m + 8)*CC + ng) = o;
                }
            }
            __syncthreads();   // chunk_mma(7) (buf1 readers) done before next pass stages buf1
        } else {
            unsigned short* Gh = (w == 1) ? g_kth : g_vth;
            unsigned short* Gl = (w == 1) ? g_ktl : g_vtl;
            for (int h4 = 0; h4 < 2; ++h4){
                __syncthreads();    // chunk_mma(7) done CTA-wide -> buf1/buf2 scratch free
                if (wn == h4){
#pragma unroll
                    for (int t = 0; t < 2; ++t){
                        const int m = wm*32 + 16*t + (lane >> 2);
#pragma unroll
                        for (int u = 0; u < 8; ++u){
                            const int nl = u*8 + 2*(lane & 3);
                            float f0 = acc[t][u][0], f1 = acc[t][u][1];
                            float f2 = acc[t][u][2], f3 = acc[t][u][3];
                            if (w == 1){ f0=elu1(f0); f1=elu1(f1); f2=elu1(f2); f3=elu1(f3); }
                            sm32[(m    )*65 + nl    ] = fsplit(f0);
                            sm32[(m    )*65 + nl + 1] = fsplit(f1);
                            sm32[(m + 8)*65 + nl    ] = fsplit(f2);
                            sm32[(m + 8)*65 + nl + 1] = fsplit(f3);
                        }
                    }
                }
                __syncthreads();
#pragma unroll
                for (int j = 0; j < 8; ++j){
                    const int np = wid + 8*j;
                    const int ng = nh*128 + h4*64 + np;
                    float ks = 0.f;
#pragma unroll
                    for (int i = 0; i < 4; ++i){
                        unsigned p = sm32[(i*32 + lane)*65 + np];
                        Gh[(size_t)ng*NN + r0 + i*32 + lane] = (unsigned short)(p & 0xffffu);
                        Gl[(size_t)ng*NN + r0 + i*32 + lane] = (unsigned short)(p >> 16);
                        if (w == 1) ks += pkval(p);
                    }
                    if (w == 1){
#pragma unroll
                        for (int o = 16; o; o >>= 1) ks += __shfl_xor_sync(0xFFFFFFFFu, ks, o);
                        if (!lane) atomicAdd(&g_ksum[ng], ks);
                    }
                }
            }
            __syncthreads();   // scratch readers done before next pass stages buf1
        }
    }
}

// ------------------------- kv = k^T v, split-K (3-stage ring, full wave) ------------------
__global__ void __launch_bounds__(256, 2) kv_mma()
{
    extern __shared__ __align__(128) unsigned char sm[];
    const unsigned sb = smem_u32(sm);
    const int tid = threadIdx.x, lane = tid & 31, wid = tid >> 5;
    const int wm = wid >> 1, wn = wid & 1;
    const int a0 = blockIdx.x << 7, b0 = blockIdx.y << 7;
    // 74 z-slices: 73 x 3584 rows (112 chunks) + 1 x 512 rows (16 chunks) = 262144
    const int NCH = (blockIdx.z < 73) ? 112 : 16;
    const size_t i0 = (size_t)blockIdx.z * 3584;
    const int row = tid >> 1, e0 = (tid & 1) << 4;
    const int c0 = (tid & 1) << 1;
    const int sws = ((row & 3) ^ ((row >> 2) & 1));
    const int sw  = ((lane & 3) ^ ((lane >> 2) & 1));
    const unsigned o1 = swoff(row, c0, sws), o2 = swoff(row, c0 + 1, sws);

    float acc[2][8][4];
#pragma unroll
    for (int t = 0; t < 2; ++t)
#pragma unroll
        for (int u = 0; u < 8; ++u)
#pragma unroll
            for (int e = 0; e < 4; ++e) acc[t][u][e] = 0.f;

    auto issue = [&](int c, int buf){
        const size_t oa = (size_t)(a0 + row)*NN + i0 + c*32 + e0;
        const size_t ob = (size_t)(b0 + row)*NN + i0 + c*32 + e0;
        const unsigned d = sb + (unsigned)(buf*SS);
        cpa16(d + PAH + o1, g_kth + oa); cpa16(d + PAH + o2, g_kth + oa + 8);
        cpa16(d + PAL + o1, g_ktl + oa); cpa16(d + PAL + o2, g_ktl + oa + 8);
        cpa16(d + PBH + o1, g_vth + ob); cpa16(d + PBH + o2, g_vth + ob + 8);
        cpa16(d + PBL + o1, g_vtl + ob); cpa16(d + PBL + o2, g_vtl + ob + 8);
        cpcommit();
    };
    issue(0, 0);
    for (int c = 0; c < NCH; ++c){
        if (c < NCH - 1){ issue(c + 1, (c + 1) % 3); cpwaitg<1>(); }
        else cpwaitg<0>();
        __syncthreads();
        chunk_mma(sb + (unsigned)((c % 3)*SS), wm, wn, lane, sw, acc);
    }
#pragma unroll
    for (int t = 0; t < 2; ++t){
        const int m = wm*32 + 16*t + (lane >> 2);
#pragma unroll
        for (int u = 0; u < 8; ++u){
            const int n = wn*64 + u*8 + 2*(lane & 3);
            atomicAdd(&g_kv[(a0 + m    )*CC + b0 + n    ], acc[t][u][0]);
            atomicAdd(&g_kv[(a0 + m    )*CC + b0 + n + 1], acc[t][u][1]);
            atomicAdd(&g_kv[(a0 + m + 8)*CC + b0 + n    ], acc[t][u][2]);
            atomicAdd(&g_kv[(a0 + m + 8)*CC + b0 + n + 1], acc[t][u][3]);
        }
    }
}

// ------------------------- Mt[j][a] = sum_b kv[a][b] Wo[j][b], split store ---------------
__global__ void __launch_bounds__(256) m_kernel(const float* __restrict__ Wo)
{
    __shared__ float wo_s[256];
    const int j = blockIdx.x, a = threadIdx.x;
    wo_s[a] = Wo[(size_t)j*CC + a];
    __syncthreads();
    const float* kvr = g_kv + (size_t)a*CC;
    float s = 0.f;
#pragma unroll 8
    for (int b = 0; b < CC; ++b) s += kvr[b] * wo_s[b];
    unsigned p = fsplit(s);
    g_mth[j*CC + a] = (unsigned short)(p & 0xffffu);
    g_mtl[j*CC + a] = (unsigned short)(p >> 16);
}

// ------------------------- out = z * (q @ Mt^T) + bo  (z fused, race-free ring) -----------
__global__ void __launch_bounds__(256, 2)
out_mma(const float* __restrict__ bo, float* __restrict__ out)
{
    extern __shared__ __align__(128) unsigned char sm[];
    const unsigned sb = smem_u32(sm);
    float* bo_s = (float*)(sm + 3*SS);
    float* ks_s = bo_s + 256;
    float* z_s  = ks_s + 256;
    const int tid = threadIdx.x, lane = tid & 31, wid = tid >> 5;
    const int wm = wid >> 1, wn = wid & 1;
    const int r0 = blockIdx.x << 7;
    const int row = tid >> 1, e0 = (tid & 1) << 4;
    const int c0 = (tid & 1) << 1;
    const int sws = ((row & 3) ^ ((row >> 2) & 1));
    const int sw  = ((lane & 3) ^ ((lane >> 2) & 1));
    const unsigned o1 = swoff(row, c0, sws), o2 = swoff(row, c0 + 1, sws);
    bo_s[tid] = bo[tid];
    ks_s[tid] = g_ksum[tid];
    __syncthreads();

    auto issueB = [&](int nh, int c, int buf){
        const size_t ob = (size_t)(nh*128 + row)*CC + c*32 + e0;
        const unsigned d = sb + (unsigned)(buf*SS);
        cpa16(d + PBH + o1, g_mth + ob); cpa16(d + PBH + o2, g_mth + ob + 8);
        cpa16(d + PBL + o1, g_mtl + ob); cpa16(d + PBL + o2, g_mtl + ob + 8);
        cpcommit();
    };

    float zacc = 0.f;
    issueB(0, 0, 0);
    for (int nh = 0; nh < 2; ++nh){
        float acc[2][8][4];
#pragma unroll
        for (int t = 0; t < 2; ++t)
#pragma unroll
            for (int u = 0; u < 8; ++u)
#pragma unroll
                for (int e = 0; e < 4; ++e) acc[t][u][e] = 0.f;

        for (int c = 0; c < 8; ++c){
            // A register staging into buf c%3 PAH/PAL (+ fused z on nh==0)
            {
                unsigned char* smb = sm + (c % 3)*SS;
                const unsigned* qs = g_qpk + (size_t)(r0 + row)*CC + c*32 + e0;
#pragma unroll
                for (int g = 0; g < 2; ++g){
                    uint4 A = *(const uint4*)(qs + g*8);
                    uint4 B = *(const uint4*)(qs + g*8 + 4);
                    unsigned p[8] = {A.x,A.y,A.z,A.w,B.x,B.y,B.z,B.w};
                    uint4 h, l;
                    h.x=(p[0]&0xffffu)|(p[1]<<16); h.y=(p[2]&0xffffu)|(p[3]<<16);
                    h.z=(p[4]&0xffffu)|(p[5]<<16); h.w=(p[6]&0xffffu)|(p[7]<<16);
                    l.x=(p[0]>>16)|(p[1]&0xffff0000u); l.y=(p[2]>>16)|(p[3]&0xffff0000u);
                    l.z=(p[4]>>16)|(p[5]&0xffff0000u); l.w=(p[6]>>16)|(p[7]&0xffff0000u);
                    const unsigned og = swoff(row, c0 + g, sws);
                    *(uint4*)(smb + PAH + og) = h;
                    *(uint4*)(smb + PAL + og) = l;
                    if (nh == 0){
                        const float* kp = ks_s + c*32 + e0 + g*8;
#pragma unroll
                        for (int u2 = 0; u2 < 8; ++u2) zacc += pkval(p[u2]) * kp[u2];
                    }
                }
            }
            if (c < 7){
                issueB(nh, c + 1, (c + 1) % 3);
                cpwaitg<1>();
                __syncthreads();
            } else {
                cpwaitg<0>();
                __syncthreads();      // ALL warps done chunk_mma(6) -> buf0 free
                if (nh == 0) issueB(1, 0, 0);   // prefetch nh=1 chunk0 into buf0
            }
            chunk_mma(sb + (unsigned)((c % 3)*SS), wm, wn, lane, sw, acc);
        }
        if (nh == 0){
            float s = zacc + __shfl_xor_sync(0xFFFFFFFFu, zacc, 1);
            if (!(tid & 1)) z_s[row] = 1.f / fmaxf(s, 1e-6f);
        }
        __syncthreads();   // z_s visible; all chunk_mma(7) done before nh=1 stages buf0 PAH

#pragma unroll
        for (int t = 0; t < 2; ++t){
            const int m = wm*32 + 16*t + (lane >> 2);
            const float z0 = z_s[m], z1 = z_s[m + 8];
#pragma unroll
            for (int u = 0; u < 8; ++u){
                const int ng = nh*128 + wn*64 + u*8 + 2*(lane & 3);
                float2 o;
                o.x = acc[t][u][0]*z0 + bo_s[ng];
                o.y = acc[t][u][1]*z0 + bo_s[ng + 1];
                *(float2*)(out + (size_t)(r0 + m)*CC + ng) = o;
                o.x = acc[t][u][2]*z1 + bo_s[ng];
                o.y = acc[t][u][3]*z1 + bo_s[ng + 1];
                *(float2*)(out + (size_t)(r0 + m + 8)*CC + ng) = o;
            }
        }
    }
}

// ------------------------- launch -------------------------
extern "C" void kernel_launch(void* const* d_in, const int* in_sizes, int n_in,
                              void* d_out, int out_size)
{
    (void)in_sizes; (void)n_in; (void)out_size;
    const float* x  = (const float*)d_in[0];
    const float* Wq = (const float*)d_in[1];
    const float* Wk = (const float*)d_in[2];
    const float* Wv = (const float*)d_in[3];
    const float* Wo = (const float*)d_in[4];
    const float* bo = (const float*)d_in[5];
    float* out = (float*)d_out;

    static int inited = 0;
    if (!inited){
        cudaFuncSetAttribute(qkv_mma, cudaFuncAttributeMaxDynamicSharedMemorySize, SMEM_DYN);
        cudaFuncSetAttribute(kv_mma,  cudaFuncAttributeMaxDynamicSharedMemorySize, SMEM_DYN);
        cudaFuncSetAttribute(out_mma, cudaFuncAttributeMaxDynamicSharedMemorySize, SMEM_DYN);
        inited = 1;
    }

    zero_kernel<<<256, 256>>>();
    presplit_w<<<192, 256>>>(Wq, Wk, Wv);
    qkv_mma<<<NN/128, 256, SMEM_DYN>>>(x);
    kv_mma<<<dim3(2, 2, 74), 256, SMEM_DYN>>>();
    m_kernel<<<256, 256>>>(Wo);
    out_mma<<<NN/128, 256, SMEM_DYN>>>(bo, out);
}

// round 16
// speedup vs baseline: 1.5740x; 1.0838x over previous
#include <cuda_runtime.h>
#include <cuda_bf16.h>
#include <math.h>

#define NN 262144
#define CC 256

// ---- gmem scratch (__device__ globals per allocation rules) ----
__device__ unsigned       g_qpk[(size_t)NN * CC];    // q packed (hi,lo bf16) [N][C]
__device__ unsigned short g_xh [(size_t)NN * CC];    // x split
__device__ unsigned short g_xl [(size_t)NN * CC];
__device__ unsigned short g_wh [3 * CC * CC];        // Wq,Wk,Wv split
__device__ unsigned short g_wl [3 * CC * CC];
__device__ unsigned short g_kth[(size_t)CC * NN];    // k^T split [C][N]
__device__ unsigned short g_ktl[(size_t)CC * NN];
__device__ unsigned short g_vth[(size_t)CC * NN];    // v^T split [C][N]
__device__ unsigned short g_vtl[(size_t)CC * NN];
__device__ unsigned short g_mth[CC * CC];            // Mt split [j][c]
__device__ unsigned short g_mtl[CC * CC];
__device__ float g_kv[CC * CC];
__device__ float g_ksum[CC];

// ---- smem: 3 stages of 4 compact planes (128 rows x 32 bf16 = 64B rows, XOR swizzle)
#define PAH  0
#define PAL  8192
#define PBH  16384
#define PBL  24576
#define SS   32768                  // bytes per stage
#define SMEM_DYN (3*SS + 3072)      // + bo/ks/z tail (out_mma) / transpose overflow (qkv)

// ------------------------- helpers -------------------------
__device__ __forceinline__ unsigned smem_u32(const void* p){
    unsigned a;
    asm("{ .reg .u64 t; cvta.to.shared.u64 t, %1; cvt.u32.u64 %0, t; }":"=r"(a):"l"(p));
    return a;
}
__device__ __forceinline__ unsigned fsplit(float f){
    __nv_bfloat16 h = __float2bfloat16(f);
    __nv_bfloat16 l = __float2bfloat16(f - __bfloat162float(h));
    return (unsigned)__bfloat16_as_ushort(h) | ((unsigned)__bfloat16_as_ushort(l) << 16);
}
__device__ __forceinline__ float pkval(unsigned p){
    return __bfloat162float(__ushort_as_bfloat16((unsigned short)(p & 0xffffu)))
         + __bfloat162float(__ushort_as_bfloat16((unsigned short)(p >> 16)));
}
__device__ __forceinline__ void cpa16(unsigned d, const void* s){
    asm volatile("cp.async.cg.shared.global [%0], [%1], 16;" :: "r"(d), "l"(s));
}
__device__ __forceinline__ void cpcommit(){ asm volatile("cp.async.commit_group;" ::: "memory"); }
template<int N>
__device__ __forceinline__ void cpwaitg(){ asm volatile("cp.async.wait_group %0;" :: "n"(N) : "memory"); }

// swizzled byte offset of 16B chunk (row, chunk) inside a 128x64B plane
// s(row) = (row&3) ^ ((row>>2)&1); invariant under row += 16.
__device__ __forceinline__ unsigned swoff(int row, int chunk, int s){
    return (unsigned)(row*64 + ((chunk ^ s) << 4));
}
__device__ __forceinline__ void ldsm4(unsigned* r, unsigned addr){
    asm volatile("ldmatrix.sync.aligned.m8n8.x4.shared.b16 {%0,%1,%2,%3}, [%4];"
        : "=r"(r[0]),"=r"(r[1]),"=r"(r[2]),"=r"(r[3]) : "r"(addr));
}
// non-volatile: pure register semantics; lets ptxas interleave MMA with LDSM
__device__ __forceinline__ void mma16816(float* c, const unsigned* a, const unsigned* b){
    asm("mma.sync.aligned.m16n8k16.row.col.f32.bf16.bf16.f32 "
        "{%0,%1,%2,%3},{%4,%5,%6,%7},{%8,%9},{%0,%1,%2,%3};"
        : "+f"(c[0]),"+f"(c[1]),"+f"(c[2]),"+f"(c[3])
        : "r"(a[0]),"r"(a[1]),"r"(a[2]),"r"(a[3]), "r"(b[0]),"r"(b[1]));
}
// one K=32 chunk: 2 k16 steps x 3 split terms over warp tile 32x64.
__device__ __forceinline__ void chunk_mma(unsigned sbase, int wm, int wn, int lane, int sw,
                                          float acc[2][8][4]){
    const int arow = wm*32 + (lane & 15);
    const int akb  = (lane >> 4) & 1;
    const int brow = wn*64 + (lane & 7) + ((lane & 16) >> 1);
    const int bkb  = (lane >> 3) & 1;
#pragma unroll
    for (int s = 0; s < 2; ++s){
        const unsigned ca = (unsigned)((((s << 1) | akb) ^ sw) << 4);
        const unsigned cb = (unsigned)((((s << 1) | bkb) ^ sw) << 4);
        unsigned ah[2][4], al[2][4], bh[8][2], bl[8][2];
#pragma unroll
        for (int t = 0; t < 2; ++t){
            unsigned base = sbase + (unsigned)((arow + 16*t)*64) + ca;
            ldsm4(ah[t], base + PAH);
            ldsm4(al[t], base + PAL);
        }
#pragma unroll
        for (int u = 0; u < 4; ++u){
            unsigned base = sbase + (unsigned)((brow + 16*u)*64) + cb;
            unsigned r[4];
            ldsm4(r, base + PBH);
            bh[2*u][0]=r[0]; bh[2*u][1]=r[1]; bh[2*u+1][0]=r[2]; bh[2*u+1][1]=r[3];
            ldsm4(r, base + PBL);
            bl[2*u][0]=r[0]; bl[2*u][1]=r[1]; bl[2*u+1][0]=r[2]; bl[2*u+1][1]=r[3];
        }
#pragma unroll
        for (int t = 0; t < 2; ++t)
#pragma unroll
            for (int u = 0; u < 8; ++u) mma16816(acc[t][u], ah[t], bh[u]);
#pragma unroll
        for (int t = 0; t < 2; ++t)
#pragma unroll
            for (int u = 0; u < 8; ++u) mma16816(acc[t][u], ah[t], bl[u]);
#pragma unroll
        for (int t = 0; t < 2; ++t)
#pragma unroll
            for (int u = 0; u < 8; ++u) mma16816(acc[t][u], al[t], bh[u]);
    }
}
__device__ __forceinline__ float elu1(float f){ return (f > 0.f) ? f + 1.f : expf(f); }

// ------------------------- presplit x and W -------------------------
__global__ void __launch_bounds__(256) presplit_x(const float* __restrict__ x)
{
    size_t i = ((size_t)blockIdx.x * 256 + threadIdx.x) * 8;
#pragma unroll
    for (int g = 0; g < 2; ++g){
        float4 v = *(const float4*)(x + i + g*4);
        unsigned p0 = fsplit(v.x), p1 = fsplit(v.y), p2 = fsplit(v.z), p3 = fsplit(v.w);
        uint2 h, l;
        h.x = (p0&0xffffu)|(p1<<16); h.y = (p2&0xffffu)|(p3<<16);
        l.x = (p0>>16)|(p1&0xffff0000u); l.y = (p2>>16)|(p3&0xffff0000u);
        *(uint2*)(g_xh + i + g*4) = h;
        *(uint2*)(g_xl + i + g*4) = l;
    }
}
__global__ void __launch_bounds__(256)
presplit_w(const float* __restrict__ Wq, const float* __restrict__ Wk,
           const float* __restrict__ Wv)
{
    int idx = blockIdx.x * 256 + threadIdx.x;
    int w = idx >> 14;
    size_t off = (size_t)w * 65536 + (size_t)(idx & 16383) * 4;
    const float* W = (w == 0) ? Wq : (w == 1) ? Wk : Wv;
    float4 v = *(const float4*)(W + (size_t)(idx & 16383) * 4);
    unsigned p0 = fsplit(v.x), p1 = fsplit(v.y), p2 = fsplit(v.z), p3 = fsplit(v.w);
    uint2 h, l;
    h.x = (p0&0xffffu)|(p1<<16); h.y = (p2&0xffffu)|(p3<<16);
    l.x = (p0>>16)|(p1&0xffff0000u); l.y = (p2>>16)|(p3&0xffff0000u);
    *(uint2*)(g_wh + off) = h;
    *(uint2*)(g_wl + off) = l;
}

__global__ void zero_kernel()
{
    int i = blockIdx.x * blockDim.x + threadIdx.x;
    if (i < CC*CC) g_kv[i] = 0.f;
    if (i < CC) g_ksum[i] = 0.f;
}

// ------------------------- qkv projections (3-stage ring, 1-phase k/v epilogue) -----------
__global__ void __launch_bounds__(256, 2)
qkv_mma()
{
    extern __shared__ __align__(128) unsigned char sm[];
    const unsigned sb = smem_u32(sm);
    // transpose scratch: buf1 + buf2 + 1KB tail (66560B, 2 halves of 128x65 words)
    unsigned* sm32 = (unsigned*)(sm + SS);
    const int tid = threadIdx.x, lane = tid & 31, wid = tid >> 5;
    const int wm = wid >> 1, wn = wid & 1;
    const int r0 = blockIdx.x << 7;
    const int row = tid >> 1, e0 = (tid & 1) << 4;   // staged elems [e0, e0+16)
    const int c0 = (tid & 1) << 1;                   // first 16B chunk
    const int sws = ((row & 3) ^ ((row >> 2) & 1));  // store-side swizzle
    const int sw  = ((lane & 3) ^ ((lane >> 2) & 1)); // load-side swizzle
    const unsigned o1 = swoff(row, c0, sws), o2 = swoff(row, c0 + 1, sws);

    auto issue = [&](int w, int nh, int c, int buf){
        const size_t oa = (size_t)(r0 + row)*CC + c*32 + e0;
        const size_t ob = (size_t)w*65536 + (size_t)(nh*128 + row)*CC + c*32 + e0;
        const unsigned d = sb + (unsigned)(buf*SS);
        cpa16(d + PAH + o1, g_xh + oa); cpa16(d + PAH + o2, g_xh + oa + 8);
        cpa16(d + PAL + o1, g_xl + oa); cpa16(d + PAL + o2, g_xl + oa + 8);
        cpa16(d + PBH + o1, g_wh + ob); cpa16(d + PBH + o2, g_wh + ob + 8);
        cpa16(d + PBL + o1, g_wl + ob); cpa16(d + PBL + o2, g_wl + ob + 8);
        cpcommit();
    };

    issue(0, 0, 0, 0);   // pass 0, chunk 0
    for (int pass = 0; pass < 6; ++pass){
        const int w = pass >> 1, nh = pass & 1;
        float acc[2][8][4];
#pragma unroll
        for (int t = 0; t < 2; ++t)
#pragma unroll
            for (int u = 0; u < 8; ++u)
#pragma unroll
                for (int e = 0; e < 4; ++e) acc[t][u][e] = 0.f;

        for (int c = 0; c < 8; ++c){
            if (c < 7){
                issue(w, nh, c + 1, (c + 1) % 3);
                cpwaitg<1>();
                __syncthreads();
            } else {
                cpwaitg<0>();
                __syncthreads();      // ALL warps done chunk_mma(6) -> buf0 free
                if (pass < 5){
                    const int np = pass + 1;   // prefetch next pass chunk 0 into buf0
                    issue(np >> 1, np & 1, 0, 0);
                }
            }
            chunk_mma(sb + (unsigned)((c % 3)*SS), wm, wn, lane, sw, acc);
        }

        if (w == 0){
#pragma unroll
            for (int t = 0; t < 2; ++t){
                const int m = wm*32 + 16*t + (lane >> 2);
#pragma unroll
                for (int u = 0; u < 8; ++u){
                    const int ng = nh*128 + wn*64 + u*8 + 2*(lane & 3);
                    uint2 o;
                    o.x = fsplit(elu1(acc[t][u][0]));
                    o.y = fsplit(elu1(acc[t][u][1]));
                    *(uint2*)(g_qpk + (size_t)(r0 + m)*CC + ng) = o;
                    o.x = fsplit(elu1(acc[t][u][2]));
                    o.y = fsplit(elu1(acc[t][u][3]));
                    *(uint2*)(g_qpk + (size_t)(r0 + m + 8)*CC + ng) = o;
                }
            }
            __syncthreads();   // chunk_mma(7) (buf1 readers) done before next pass issues buf1
        } else {
            unsigned short* Gh = (w == 1) ? g_kth : g_vth;
            unsigned short* Gl = (w == 1) ? g_ktl : g_vtl;
            __syncthreads();    // chunk_mma(7) done CTA-wide -> scratch region free
            // single-phase transpose: each warp writes its own wn half (region wn*8320 words)
            {
                unsigned* scr = sm32 + wn*8320;
#pragma unroll
                for (int t = 0; t < 2; ++t){
                    const int m = wm*32 + 16*t + (lane >> 2);
#pragma unroll
                    for (int u = 0; u < 8; ++u){
                        const int nl = u*8 + 2*(lane & 3);
                        float f0 = acc[t][u][0], f1 = acc[t][u][1];
                        float f2 = acc[t][u][2], f3 = acc[t][u][3];
                        if (w == 1){ f0=elu1(f0); f1=elu1(f1); f2=elu1(f2); f3=elu1(f3); }
                        scr[(m    )*65 + nl    ] = fsplit(f0);
                        scr[(m    )*65 + nl + 1] = fsplit(f1);
                        scr[(m + 8)*65 + nl    ] = fsplit(f2);
                        scr[(m + 8)*65 + nl + 1] = fsplit(f3);
                    }
                }
            }
            __syncthreads();
            // flush: row-pair packed 4B stores, 128B/warp coalesced
#pragma unroll
            for (int j = 0; j < 16; ++j){
                const int np = wid + 8*j;               // 0..127
                const unsigned* scr = sm32 + (np >> 6)*8320;
                const int nl = np & 63;
                const int ng = nh*128 + np;
                float ks = 0.f;
#pragma unroll
                for (int i = 0; i < 2; ++i){
                    const int r = i*64 + 2*lane;
                    unsigned p0 = scr[(r    )*65 + nl];
                    unsigned p1 = scr[(r + 1)*65 + nl];
                    unsigned hp = (p0 & 0xffffu) | (p1 << 16);
                    unsigned lp = (p0 >> 16) | (p1 & 0xffff0000u);
                    *(unsigned*)(Gh + (size_t)ng*NN + r0 + r) = hp;
                    *(unsigned*)(Gl + (size_t)ng*NN + r0 + r) = lp;
                    if (w == 1) ks += pkval(p0) + pkval(p1);
                }
                if (w == 1){
#pragma unroll
                    for (int o = 16; o; o >>= 1) ks += __shfl_xor_sync(0xFFFFFFFFu, ks, o);
                    if (!lane) atomicAdd(&g_ksum[ng], ks);
                }
            }
            __syncthreads();   // scratch readers done before next pass issues buf1
        }
    }
}

// ------------------------- kv = k^T v, split-K (3-stage ring, full wave) ------------------
__global__ void __launch_bounds__(256, 2) kv_mma()
{
    extern __shared__ __align__(128) unsigned char sm[];
    const unsigned sb = smem_u32(sm);
    const int tid = threadIdx.x, lane = tid & 31, wid = tid >> 5;
    const int wm = wid >> 1, wn = wid & 1;
    const int a0 = blockIdx.x << 7, b0 = blockIdx.y << 7;
    // 74 z-slices: 73 x 3584 rows (112 chunks) + 1 x 512 rows (16 chunks) = 262144
    const int NCH = (blockIdx.z < 73) ? 112 : 16;
    const size_t i0 = (size_t)blockIdx.z * 3584;
    const int row = tid >> 1, e0 = (tid & 1) << 4;
    const int c0 = (tid & 1) << 1;
    const int sws = ((row & 3) ^ ((row >> 2) & 1));
    const int sw  = ((lane & 3) ^ ((lane >> 2) & 1));
    const unsigned o1 = swoff(row, c0, sws), o2 = swoff(row, c0 + 1, sws);

    float acc[2][8][4];
#pragma unroll
    for (int t = 0; t < 2; ++t)
#pragma unroll
        for (int u = 0; u < 8; ++u)
#pragma unroll
            for (int e = 0; e < 4; ++e) acc[t][u][e] = 0.f;

    auto issue = [&](int c, int buf){
        const size_t oa = (size_t)(a0 + row)*NN + i0 + c*32 + e0;
        const size_t ob = (size_t)(b0 + row)*NN + i0 + c*32 + e0;
        const unsigned d = sb + (unsigned)(buf*SS);
        cpa16(d + PAH + o1, g_kth + oa); cpa16(d + PAH + o2, g_kth + oa + 8);
        cpa16(d + PAL + o1, g_ktl + oa); cpa16(d + PAL + o2, g_ktl + oa + 8);
        cpa16(d + PBH + o1, g_vth + ob); cpa16(d + PBH + o2, g_vth + ob + 8);
        cpa16(d + PBL + o1, g_vtl + ob); cpa16(d + PBL + o2, g_vtl + ob + 8);
        cpcommit();
    };
    issue(0, 0);
    for (int c = 0; c < NCH; ++c){
        if (c < NCH - 1){ issue(c + 1, (c + 1) % 3); cpwaitg<1>(); }
        else cpwaitg<0>();
        __syncthreads();
        chunk_mma(sb + (unsigned)((c % 3)*SS), wm, wn, lane, sw, acc);
    }
#pragma unroll
    for (int t = 0; t < 2; ++t){
        const int m = wm*32 + 16*t + (lane >> 2);
#pragma unroll
        for (int u = 0; u < 8; ++u){
            const int n = wn*64 + u*8 + 2*(lane & 3);
            atomicAdd(&g_kv[(a0 + m    )*CC + b0 + n    ], acc[t][u][0]);
            atomicAdd(&g_kv[(a0 + m    )*CC + b0 + n + 1], acc[t][u][1]);
            atomicAdd(&g_kv[(a0 + m + 8)*CC + b0 + n    ], acc[t][u][2]);
            atomicAdd(&g_kv[(a0 + m + 8)*CC + b0 + n + 1], acc[t][u][3]);
        }
    }
}

// ------------------------- Mt[j][a] = sum_b kv[a][b] Wo[j][b], split store ---------------
__global__ void __launch_bounds__(256) m_kernel(const float* __restrict__ Wo)
{
    __shared__ float wo_s[256];
    const int j = blockIdx.x, a = threadIdx.x;
    wo_s[a] = Wo[(size_t)j*CC + a];
    __syncthreads();
    const float* kvr = g_kv + (size_t)a*CC;
    float s = 0.f;
#pragma unroll 8
    for (int b = 0; b < CC; ++b) s += kvr[b] * wo_s[b];
    unsigned p = fsplit(s);
    g_mth[j*CC + a] = (unsigned short)(p & 0xffffu);
    g_mtl[j*CC + a] = (unsigned short)(p >> 16);
}

// ------------------------- out = z * (q @ Mt^T) + bo  (z fused, race-free ring) -----------
__global__ void __launch_bounds__(256, 2)
out_mma(const float* __restrict__ bo, float* __restrict__ out)
{
    extern __shared__ __align__(128) unsigned char sm[];
    const unsigned sb = smem_u32(sm);
    float* bo_s = (float*)(sm + 3*SS);
    float* ks_s = bo_s + 256;
    float* z_s  = ks_s + 256;
    const int tid = threadIdx.x, lane = tid & 31, wid = tid >> 5;
    const int wm = wid >> 1, wn = wid & 1;
    const int r0 = blockIdx.x << 7;
    const int row = tid >> 1, e0 = (tid & 1) << 4;
    const int c0 = (tid & 1) << 1;
    const int sws = ((row & 3) ^ ((row >> 2) & 1));
    const int sw  = ((lane & 3) ^ ((lane >> 2) & 1));
    const unsigned o1 = swoff(row, c0, sws), o2 = swoff(row, c0 + 1, sws);
    bo_s[tid] = bo[tid];
    ks_s[tid] = g_ksum[tid];
    __syncthreads();

    auto issueB = [&](int nh, int c, int buf){
        const size_t ob = (size_t)(nh*128 + row)*CC + c*32 + e0;
        const unsigned d = sb + (unsigned)(buf*SS);
        cpa16(d + PBH + o1, g_mth + ob); cpa16(d + PBH + o2, g_mth + ob + 8);
        cpa16(d + PBL + o1, g_mtl + ob); cpa16(d + PBL + o2, g_mtl + ob + 8);
        cpcommit();
    };

    float zacc = 0.f;
    issueB(0, 0, 0);
    for (int nh = 0; nh < 2; ++nh){
        float acc[2][8][4];
#pragma unroll
        for (int t = 0; t < 2; ++t)
#pragma unroll
            for (int u = 0; u < 8; ++u)
#pragma unroll
                for (int e = 0; e < 4; ++e) acc[t][u][e] = 0.f;

        for (int c = 0; c < 8; ++c){
            // A register staging into buf c%3 PAH/PAL (+ fused z on nh==0); safe:
            // that buffer's PAH/PAL last readers (chunk c-3) finished before B(c-1).
            {
                unsigned char* smb = sm + (c % 3)*SS;
                const unsigned* qs = g_qpk + (size_t)(r0 + row)*CC + c*32 + e0;
#pragma unroll
                for (int g = 0; g < 2; ++g){
                    uint4 A = *(const uint4*)(qs + g*8);
                    uint4 B = *(const uint4*)(qs + g*8 + 4);
                    unsigned p[8] = {A.x,A.y,A.z,A.w,B.x,B.y,B.z,B.w};
                    uint4 h, l;
                    h.x=(p[0]&0xffffu)|(p[1]<<16); h.y=(p[2]&0xffffu)|(p[3]<<16);
                    h.z=(p[4]&0xffffu)|(p[5]<<16); h.w=(p[6]&0xffffu)|(p[7]<<16);
                    l.x=(p[0]>>16)|(p[1]&0xffff0000u); l.y=(p[2]>>16)|(p[3]&0xffff0000u);
                    l.z=(p[4]>>16)|(p[5]&0xffff0000u); l.w=(p[6]>>16)|(p[7]&0xffff0000u);
                    const unsigned og = swoff(row, c0 + g, sws);
                    *(uint4*)(smb + PAH + og) = h;
                    *(uint4*)(smb + PAL + og) = l;
                    if (nh == 0){
                        const float* kp = ks_s + c*32 + e0 + g*8;
#pragma unroll
                        for (int u2 = 0; u2 < 8; ++u2) zacc += pkval(p[u2]) * kp[u2];
                    }
                }
            }
            if (c < 7){
                issueB(nh, c + 1, (c + 1) % 3);
                cpwaitg<1>();
                __syncthreads();
            } else {
                cpwaitg<0>();
                __syncthreads();      // ALL warps done chunk_mma(6) -> buf0 free
                if (nh == 0) issueB(1, 0, 0);   // prefetch nh=1 chunk0 into buf0
            }
            chunk_mma(sb + (unsigned)((c % 3)*SS), wm, wn, lane, sw, acc);
        }
        if (nh == 0){
            float s = zacc + __shfl_xor_sync(0xFFFFFFFFu, zacc, 1);
            if (!(tid & 1)) z_s[row] = 1.f / fmaxf(s, 1e-6f);
        }
        __syncthreads();   // z_s visible; all chunk_mma(7) done before nh=1 stages buf0 PAH

#pragma unroll
        for (int t = 0; t < 2; ++t){
            const int m = wm*32 + 16*t + (lane >> 2);
            const float z0 = z_s[m], z1 = z_s[m + 8];
#pragma unroll
            for (int u = 0; u < 8; ++u){
                const int ng = nh*128 + wn*64 + u*8 + 2*(lane & 3);
                float2 o;
                o.x = acc[t][u][0]*z0 + bo_s[ng];
                o.y = acc[t][u][1]*z0 + bo_s[ng + 1];
                *(float2*)(out + (size_t)(r0 + m)*CC + ng) = o;
                o.x = acc[t][u][2]*z1 + bo_s[ng];
                o.y = acc[t][u][3]*z1 + bo_s[ng + 1];
                *(float2*)(out + (size_t)(r0 + m + 8)*CC + ng) = o;
            }
        }
    }
}

// ------------------------- launch -------------------------
extern "C" void kernel_launch(void* const* d_in, const int* in_sizes, int n_in,
                              void* d_out, int out_size)
{
    (void)in_sizes; (void)n_in; (void)out_size;
    const float* x  = (const float*)d_in[0];
    const float* Wq = (const float*)d_in[1];
    const float* Wk = (const float*)d_in[2];
    const float* Wv = (const float*)d_in[3];
    const float* Wo = (const float*)d_in[4];
    const float* bo = (const float*)d_in[5];
    float* out = (float*)d_out;

    static int inited = 0;
    if (!inited){
        cudaFuncSetAttribute(qkv_mma, cudaFuncAttributeMaxDynamicSharedMemorySize, SMEM_DYN);
        cudaFuncSetAttribute(kv_mma,  cudaFuncAttributeMaxDynamicSharedMemorySize, SMEM_DYN);
        cudaFuncSetAttribute(out_mma, cudaFuncAttributeMaxDynamicSharedMemorySize, SMEM_DYN);
        inited = 1;
    }

    zero_kernel<<<256, 256>>>();
    presplit_x<<<32768, 256>>>(x);
    presplit_w<<<192, 256>>>(Wq, Wk, Wv);
    qkv_mma<<<NN/128, 256, SMEM_DYN>>>();
    kv_mma<<<dim3(2, 2, 74), 256, SMEM_DYN>>>();
    m_kernel<<<256, 256>>>(Wo);
    out_mma<<<NN/128, 256, SMEM_DYN>>>(bo, out);
}

// round 17
// speedup vs baseline: 1.5782x; 1.0027x over previous
#include <cuda_runtime.h>
#include <cuda_bf16.h>
#include <math.h>

#define NN 262144
#define CC 256

// ---- gmem scratch (__device__ globals per allocation rules) ----
__device__ unsigned       g_qpk[(size_t)NN * CC];    // q packed (hi,lo bf16) [N][C]
__device__ unsigned short g_xh [(size_t)NN * CC];    // x split
__device__ unsigned short g_xl [(size_t)NN * CC];
__device__ unsigned short g_wh [3 * CC * CC];        // Wq,Wk,Wv split
__device__ unsigned short g_wl [3 * CC * CC];
__device__ unsigned short g_kh [(size_t)NN * CC];    // k split, natural [N][C]
__device__ unsigned short g_kl [(size_t)NN * CC];
__device__ unsigned short g_vh [(size_t)NN * CC];    // v split, natural [N][C]
__device__ unsigned short g_vl [(size_t)NN * CC];
__device__ unsigned short g_mth[CC * CC];            // Mt split [j][c]
__device__ unsigned short g_mtl[CC * CC];
__device__ float g_kv[CC * CC];
__device__ float g_ksum[CC];

// ---- smem: 3 stages of 4 planes. qkv/out: 128 rows x 64B; kv: 32 rows x 256B.
#define PAH  0
#define PAL  8192
#define PBH  16384
#define PBL  24576
#define SS   32768                  // bytes per stage
#define SMEM_DYN (3*SS + 3072)      // + bo/ks/z tail for out_mma

// ------------------------- helpers -------------------------
__device__ __forceinline__ unsigned smem_u32(const void* p){
    unsigned a;
    asm("{ .reg .u64 t; cvta.to.shared.u64 t, %1; cvt.u32.u64 %0, t; }":"=r"(a):"l"(p));
    return a;
}
__device__ __forceinline__ unsigned fsplit(float f){
    __nv_bfloat16 h = __float2bfloat16(f);
    __nv_bfloat16 l = __float2bfloat16(f - __bfloat162float(h));
    return (unsigned)__bfloat16_as_ushort(h) | ((unsigned)__bfloat16_as_ushort(l) << 16);
}
__device__ __forceinline__ float pkval(unsigned p){
    return __bfloat162float(__ushort_as_bfloat16((unsigned short)(p & 0xffffu)))
         + __bfloat162float(__ushort_as_bfloat16((unsigned short)(p >> 16)));
}
__device__ __forceinline__ void cpa16(unsigned d, const void* s){
    asm volatile("cp.async.cg.shared.global [%0], [%1], 16;" :: "r"(d), "l"(s));
}
__device__ __forceinline__ void cpcommit(){ asm volatile("cp.async.commit_group;" ::: "memory"); }
template<int N>
__device__ __forceinline__ void cpwaitg(){ asm volatile("cp.async.wait_group %0;" :: "n"(N) : "memory"); }

// swizzled byte offset of 16B chunk (row, chunk) inside a 128x64B plane (qkv/out)
__device__ __forceinline__ unsigned swoff(int row, int chunk, int s){
    return (unsigned)(row*64 + ((chunk ^ s) << 4));
}
__device__ __forceinline__ void ldsm4(unsigned* r, unsigned addr){
    asm volatile("ldmatrix.sync.aligned.m8n8.x4.shared.b16 {%0,%1,%2,%3}, [%4];"
        : "=r"(r[0]),"=r"(r[1]),"=r"(r[2]),"=r"(r[3]) : "r"(addr));
}
__device__ __forceinline__ void ldsm4t(unsigned* r, unsigned addr){
    asm volatile("ldmatrix.sync.aligned.m8n8.x4.trans.shared.b16 {%0,%1,%2,%3}, [%4];"
        : "=r"(r[0]),"=r"(r[1]),"=r"(r[2]),"=r"(r[3]) : "r"(addr));
}
// non-volatile: pure register semantics; lets ptxas interleave MMA with LDSM
__device__ __forceinline__ void mma16816(float* c, const unsigned* a, const unsigned* b){
    asm("mma.sync.aligned.m16n8k16.row.col.f32.bf16.bf16.f32 "
        "{%0,%1,%2,%3},{%4,%5,%6,%7},{%8,%9},{%0,%1,%2,%3};"
        : "+f"(c[0]),"+f"(c[1]),"+f"(c[2]),"+f"(c[3])
        : "r"(a[0]),"r"(a[1]),"r"(a[2]),"r"(a[3]), "r"(b[0]),"r"(b[1]));
}
// one K=32 chunk: 2 k16 steps x 3 split terms over warp tile 32x64 (64B-row planes).
__device__ __forceinline__ void chunk_mma(unsigned sbase, int wm, int wn, int lane, int sw,
                                          float acc[2][8][4]){
    const int arow = wm*32 + (lane & 15);
    const int akb  = (lane >> 4) & 1;
    const int brow = wn*64 + (lane & 7) + ((lane & 16) >> 1);
    const int bkb  = (lane >> 3) & 1;
#pragma unroll
    for (int s = 0; s < 2; ++s){
        const unsigned ca = (unsigned)((((s << 1) | akb) ^ sw) << 4);
        const unsigned cb = (unsigned)((((s << 1) | bkb) ^ sw) << 4);
        unsigned ah[2][4], al[2][4], bh[8][2], bl[8][2];
#pragma unroll
        for (int t = 0; t < 2; ++t){
            unsigned base = sbase + (unsigned)((arow + 16*t)*64) + ca;
            ldsm4(ah[t], base + PAH);
            ldsm4(al[t], base + PAL);
        }
#pragma unroll
        for (int u = 0; u < 4; ++u){
            unsigned base = sbase + (unsigned)((brow + 16*u)*64) + cb;
            unsigned r[4];
            ldsm4(r, base + PBH);
            bh[2*u][0]=r[0]; bh[2*u][1]=r[1]; bh[2*u+1][0]=r[2]; bh[2*u+1][1]=r[3];
            ldsm4(r, base + PBL);
            bl[2*u][0]=r[0]; bl[2*u][1]=r[1]; bl[2*u+1][0]=r[2]; bl[2*u+1][1]=r[3];
        }
#pragma unroll
        for (int t = 0; t < 2; ++t)
#pragma unroll
            for (int u = 0; u < 8; ++u) mma16816(acc[t][u], ah[t], bh[u]);
#pragma unroll
        for (int t = 0; t < 2; ++t)
#pragma unroll
            for (int u = 0; u < 8; ++u) mma16816(acc[t][u], ah[t], bl[u]);
#pragma unroll
        for (int t = 0; t < 2; ++t)
#pragma unroll
            for (int u = 0; u < 8; ++u) mma16816(acc[t][u], al[t], bh[u]);
    }
}
// kv variant: operands in natural [i][col] 32x256B planes, trans-ldmatrix.
// swizzle: chunk ^= (row & 7).
__device__ __forceinline__ void chunk_mma_t(unsigned sbase, int wm, int wn, int lane,
                                            float acc[2][8][4]){
    const int air = ((lane >> 4) & 1)*8 + (lane & 7);   // A source i-row
    const int acb = (lane >> 3) & 1;                    // A chunk low bit (a8)
    const int bir = ((lane >> 3) & 1)*8 + (lane & 7);   // B source i-row
    const int bcb = (lane >> 4) & 1;                    // B chunk low bit (n8)
#pragma unroll
    for (int s = 0; s < 2; ++s){
        const int ra = s*16 + air, rb = s*16 + bir;
        unsigned ah[2][4], al[2][4], bh[8][2], bl[8][2];
#pragma unroll
        for (int t = 0; t < 2; ++t){
            const int ch = wm*4 + 2*t + acb;
            unsigned base = sbase + (unsigned)(ra*256 + ((ch ^ (ra & 7)) << 4));
            ldsm4t(ah[t], base + PAH);
            ldsm4t(al[t], base + PAL);
        }
#pragma unroll
        for (int u = 0; u < 4; ++u){
            const int ch = wn*8 + 2*u + bcb;
            unsigned base = sbase + (unsigned)(rb*256 + ((ch ^ (rb & 7)) << 4));
            unsigned r[4];
            ldsm4t(r, base + PBH);
            bh[2*u][0]=r[0]; bh[2*u][1]=r[1]; bh[2*u+1][0]=r[2]; bh[2*u+1][1]=r[3];
            ldsm4t(r, base + PBL);
            bl[2*u][0]=r[0]; bl[2*u][1]=r[1]; bl[2*u+1][0]=r[2]; bl[2*u+1][1]=r[3];
        }
#pragma unroll
        for (int t = 0; t < 2; ++t)
#pragma unroll
            for (int u = 0; u < 8; ++u) mma16816(acc[t][u], ah[t], bh[u]);
#pragma unroll
        for (int t = 0; t < 2; ++t)
#pragma unroll
            for (int u = 0; u < 8; ++u) mma16816(acc[t][u], ah[t], bl[u]);
#pragma unroll
        for (int t = 0; t < 2; ++t)
#pragma unroll
            for (int u = 0; u < 8; ++u) mma16816(acc[t][u], al[t], bh[u]);
    }
}
__device__ __forceinline__ float elu1(float f){ return (f > 0.f) ? f + 1.f : expf(f); }

// ------------------------- presplit x and W -------------------------
__global__ void __launch_bounds__(256) presplit_x(const float* __restrict__ x)
{
    size_t i = ((size_t)blockIdx.x * 256 + threadIdx.x) * 8;
#pragma unroll
    for (int g = 0; g < 2; ++g){
        float4 v = *(const float4*)(x + i + g*4);
        unsigned p0 = fsplit(v.x), p1 = fsplit(v.y), p2 = fsplit(v.z), p3 = fsplit(v.w);
        uint2 h, l;
        h.x = (p0&0xffffu)|(p1<<16); h.y = (p2&0xffffu)|(p3<<16);
        l.x = (p0>>16)|(p1&0xffff0000u); l.y = (p2>>16)|(p3&0xffff0000u);
        *(uint2*)(g_xh + i + g*4) = h;
        *(uint2*)(g_xl + i + g*4) = l;
    }
}
__global__ void __launch_bounds__(256)
presplit_w(const float* __restrict__ Wq, const float* __restrict__ Wk,
           const float* __restrict__ Wv)
{
    int idx = blockIdx.x * 256 + threadIdx.x;
    int w = idx >> 14;
    size_t off = (size_t)w * 65536 + (size_t)(idx & 16383) * 4;
    const float* W = (w == 0) ? Wq : (w == 1) ? Wk : Wv;
    float4 v = *(const float4*)(W + (size_t)(idx & 16383) * 4);
    unsigned p0 = fsplit(v.x), p1 = fsplit(v.y), p2 = fsplit(v.z), p3 = fsplit(v.w);
    uint2 h, l;
    h.x = (p0&0xffffu)|(p1<<16); h.y = (p2&0xffffu)|(p3<<16);
    l.x = (p0>>16)|(p1&0xffff0000u); l.y = (p2>>16)|(p3&0xffff0000u);
    *(uint2*)(g_wh + off) = h;
    *(uint2*)(g_wl + off) = l;
}

__global__ void zero_kernel()
{
    int i = blockIdx.x * blockDim.x + threadIdx.x;
    if (i < CC*CC) g_kv[i] = 0.f;
    if (i < CC) g_ksum[i] = 0.f;
}

// ------------------------- qkv projections (3-stage ring, direct k/v stores) --------------
__global__ void __launch_bounds__(256, 2)
qkv_mma()
{
    extern __shared__ __align__(128) unsigned char sm[];
    const unsigned sb = smem_u32(sm);
    const int tid = threadIdx.x, lane = tid & 31, wid = tid >> 5;
    const int wm = wid >> 1, wn = wid & 1;
    const int r0 = blockIdx.x << 7;
    const int row = tid >> 1, e0 = (tid & 1) << 4;   // staged elems [e0, e0+16)
    const int c0 = (tid & 1) << 1;                   // first 16B chunk
    const int sws = ((row & 3) ^ ((row >> 2) & 1));  // store-side swizzle
    const int sw  = ((lane & 3) ^ ((lane >> 2) & 1)); // load-side swizzle
    const unsigned o1 = swoff(row, c0, sws), o2 = swoff(row, c0 + 1, sws);

    auto issue = [&](int w, int nh, int c, int buf){
        const size_t oa = (size_t)(r0 + row)*CC + c*32 + e0;
        const size_t ob = (size_t)w*65536 + (size_t)(nh*128 + row)*CC + c*32 + e0;
        const unsigned d = sb + (unsigned)(buf*SS);
        cpa16(d + PAH + o1, g_xh + oa); cpa16(d + PAH + o2, g_xh + oa + 8);
        cpa16(d + PAL + o1, g_xl + oa); cpa16(d + PAL + o2, g_xl + oa + 8);
        cpa16(d + PBH + o1, g_wh + ob); cpa16(d + PBH + o2, g_wh + ob + 8);
        cpa16(d + PBL + o1, g_wl + ob); cpa16(d + PBL + o2, g_wl + ob + 8);
        cpcommit();
    };

    issue(0, 0, 0, 0);   // pass 0, chunk 0
    for (int pass = 0; pass < 6; ++pass){
        const int w = pass >> 1, nh = pass & 1;
        float acc[2][8][4];
#pragma unroll
        for (int t = 0; t < 2; ++t)
#pragma unroll
            for (int u = 0; u < 8; ++u)
#pragma unroll
                for (int e = 0; e < 4; ++e) acc[t][u][e] = 0.f;

        for (int c = 0; c < 8; ++c){
            if (c < 7){
                issue(w, nh, c + 1, (c + 1) % 3);
                cpwaitg<1>();
                __syncthreads();
            } else {
                cpwaitg<0>();
                __syncthreads();      // ALL warps done chunk_mma(6) -> buf0 free
                if (pass < 5){
                    const int np = pass + 1;   // prefetch next pass chunk 0 into buf0
                    issue(np >> 1, np & 1, 0, 0);
                }
            }
            chunk_mma(sb + (unsigned)((c % 3)*SS), wm, wn, lane, sw, acc);
        }

        if (w == 0){
#pragma unroll
            for (int t = 0; t < 2; ++t){
                const int m = wm*32 + 16*t + (lane >> 2);
#pragma unroll
                for (int u = 0; u < 8; ++u){
                    const int ng = nh*128 + wn*64 + u*8 + 2*(lane & 3);
                    uint2 o;
                    o.x = fsplit(elu1(acc[t][u][0]));
                    o.y = fsplit(elu1(acc[t][u][1]));
                    *(uint2*)(g_qpk + (size_t)(r0 + m)*CC + ng) = o;
                    o.x = fsplit(elu1(acc[t][u][2]));
                    o.y = fsplit(elu1(acc[t][u][3]));
                    *(uint2*)(g_qpk + (size_t)(r0 + m + 8)*CC + ng) = o;
                }
            }
        } else {
            // direct [N][C] hi/lo split stores (no transpose) + fused ksum (k only)
            unsigned short* Gh = (w == 1) ? g_kh : g_vh;
            unsigned short* Gl = (w == 1) ? g_kl : g_vl;
            float csum[16];
#pragma unroll
            for (int j = 0; j < 16; ++j) csum[j] = 0.f;
#pragma unroll
            for (int t = 0; t < 2; ++t){
                const int m = wm*32 + 16*t + (lane >> 2);
#pragma unroll
                for (int u = 0; u < 8; ++u){
                    const int ng = nh*128 + wn*64 + u*8 + 2*(lane & 3);
                    float f0 = acc[t][u][0], f1 = acc[t][u][1];
                    float f2 = acc[t][u][2], f3 = acc[t][u][3];
                    if (w == 1){
                        f0 = elu1(f0); f1 = elu1(f1); f2 = elu1(f2); f3 = elu1(f3);
                        csum[2*u]   += f0 + f2;
                        csum[2*u+1] += f1 + f3;
                    }
                    unsigned p0 = fsplit(f0), p1 = fsplit(f1);
                    unsigned p2 = fsplit(f2), p3 = fsplit(f3);
                    *(unsigned*)(Gh + (size_t)(r0 + m)*CC + ng)     = (p0 & 0xffffu) | (p1 << 16);
                    *(unsigned*)(Gl + (size_t)(r0 + m)*CC + ng)     = (p0 >> 16) | (p1 & 0xffff0000u);
                    *(unsigned*)(Gh + (size_t)(r0 + m + 8)*CC + ng) = (p2 & 0xffffu) | (p3 << 16);
                    *(unsigned*)(Gl + (size_t)(r0 + m + 8)*CC + ng) = (p2 >> 16) | (p3 & 0xffff0000u);
                }
            }
            if (w == 1){
#pragma unroll
                for (int j = 0; j < 16; ++j){
                    csum[j] += __shfl_xor_sync(0xFFFFFFFFu, csum[j], 4);
                    csum[j] += __shfl_xor_sync(0xFFFFFFFFu, csum[j], 8);
                    csum[j] += __shfl_xor_sync(0xFFFFFFFFu, csum[j], 16);
                }
                if (lane < 4){
#pragma unroll
                    for (int u = 0; u < 8; ++u){
                        const int ng = nh*128 + wn*64 + u*8 + 2*lane;
                        atomicAdd(&g_ksum[ng],     csum[2*u]);
                        atomicAdd(&g_ksum[ng + 1], csum[2*u+1]);
                    }
                }
            }
        }
        __syncthreads();   // chunk_mma(7) (buf1 readers) done before next pass issues buf1
    }
}

// ------------------------- kv = k^T v, split-K (natural layout, trans-ldmatrix) -----------
__global__ void __launch_bounds__(256, 2) kv_mma()
{
    extern __shared__ __align__(128) unsigned char sm[];
    const unsigned sb = smem_u32(sm);
    const int tid = threadIdx.x, lane = tid & 31, wid = tid >> 5;
    const int wm = wid >> 1, wn = wid & 1;
    const int a0 = blockIdx.x << 7, b0 = blockIdx.y << 7;
    // 74 z-slices: 73 x 3584 rows (112 chunks) + 1 x 512 rows (16 chunks) = 262144
    const int NCH = (blockIdx.z < 73) ? 112 : 16;
    const size_t i0 = (size_t)blockIdx.z * 3584;
    // staging: thread -> source row (tid>>3, 0..31), chunk pair (tid&7)*2
    const int srow = tid >> 3, sc0 = (tid & 7) << 1;
    const unsigned so1 = (unsigned)(srow*256 + ((sc0 ^ (srow & 7)) << 4));
    const unsigned so2 = (unsigned)(srow*256 + (((sc0 + 1) ^ (srow & 7)) << 4));

    float acc[2][8][4];
#pragma unroll
    for (int t = 0; t < 2; ++t)
#pragma unroll
        for (int u = 0; u < 8; ++u)
#pragma unroll
            for (int e = 0; e < 4; ++e) acc[t][u][e] = 0.f;

    auto issue = [&](int c, int buf){
        const size_t ka = (size_t)(i0 + c*32 + srow)*CC + a0 + sc0*8;
        const size_t vb = (size_t)(i0 + c*32 + srow)*CC + b0 + sc0*8;
        const unsigned d = sb + (unsigned)(buf*SS);
        cpa16(d + PAH + so1, g_kh + ka); cpa16(d + PAH + so2, g_kh + ka + 8);
        cpa16(d + PAL + so1, g_kl + ka); cpa16(d + PAL + so2, g_kl + ka + 8);
        cpa16(d + PBH + so1, g_vh + vb); cpa16(d + PBH + so2, g_vh + vb + 8);
        cpa16(d + PBL + so1, g_vl + vb); cpa16(d + PBL + so2, g_vl + vb + 8);
        cpcommit();
    };
    issue(0, 0);
    for (int c = 0; c < NCH; ++c){
        if (c < NCH - 1){ issue(c + 1, (c + 1) % 3); cpwaitg<1>(); }
        else cpwaitg<0>();
        __syncthreads();
        chunk_mma_t(sb + (unsigned)((c % 3)*SS), wm, wn, lane, acc);
    }
#pragma unroll
    for (int t = 0; t < 2; ++t){
        const int m = wm*32 + 16*t + (lane >> 2);
#pragma unroll
        for (int u = 0; u < 8; ++u){
            const int n = wn*64 + u*8 + 2*(lane & 3);
            atomicAdd(&g_kv[(a0 + m    )*CC + b0 + n    ], acc[t][u][0]);
            atomicAdd(&g_kv[(a0 + m    )*CC + b0 + n + 1], acc[t][u][1]);
            atomicAdd(&g_kv[(a0 + m + 8)*CC + b0 + n    ], acc[t][u][2]);
            atomicAdd(&g_kv[(a0 + m + 8)*CC + b0 + n + 1], acc[t][u][3]);
        }
    }
}

// ------------------------- Mt[j][a] = sum_b kv[a][b] Wo[j][b], split store ---------------
__global__ void __launch_bounds__(256) m_kernel(const float* __restrict__ Wo)
{
    __shared__ float wo_s[256];
    const int j = blockIdx.x, a = threadIdx.x;
    wo_s[a] = Wo[(size_t)j*CC + a];
    __syncthreads();
    const float* kvr = g_kv + (size_t)a*CC;
    float s = 0.f;
#pragma unroll 8
    for (int b = 0; b < CC; ++b) s += kvr[b] * wo_s[b];
    unsigned p = fsplit(s);
    g_mth[j*CC + a] = (unsigned short)(p & 0xffffu);
    g_mtl[j*CC + a] = (unsigned short)(p >> 16);
}

// ------------------------- out = z * (q @ Mt^T) + bo  (z fused, race-free ring) -----------
__global__ void __launch_bounds__(256, 2)
out_mma(const float* __restrict__ bo, float* __restrict__ out)
{
    extern __shared__ __align__(128) unsigned char sm[];
    const unsigned sb = smem_u32(sm);
    float* bo_s = (float*)(sm + 3*SS);
    float* ks_s = bo_s + 256;
    float* z_s  = ks_s + 256;
    const int tid = threadIdx.x, lane = tid & 31, wid = tid >> 5;
    const int wm = wid >> 1, wn = wid & 1;
    const int r0 = blockIdx.x << 7;
    const int row = tid >> 1, e0 = (tid & 1) << 4;
    const int c0 = (tid & 1) << 1;
    const int sws = ((row & 3) ^ ((row >> 2) & 1));
    const int sw  = ((lane & 3) ^ ((lane >> 2) & 1));
    const unsigned o1 = swoff(row, c0, sws), o2 = swoff(row, c0 + 1, sws);
    bo_s[tid] = bo[tid];
    ks_s[tid] = g_ksum[tid];
    __syncthreads();

    auto issueB = [&](int nh, int c, int buf){
        const size_t ob = (size_t)(nh*128 + row)*CC + c*32 + e0;
        const unsigned d = sb + (unsigned)(buf*SS);
        cpa16(d + PBH + o1, g_mth + ob); cpa16(d + PBH + o2, g_mth + ob + 8);
        cpa16(d + PBL + o1, g_mtl + ob); cpa16(d + PBL + o2, g_mtl + ob + 8);
        cpcommit();
    };

    float zacc = 0.f;
    issueB(0, 0, 0);
    for (int nh = 0; nh < 2; ++nh){
        float acc[2][8][4];
#pragma unroll
        for (int t = 0; t < 2; ++t)
#pragma unroll
            for (int u = 0; u < 8; ++u)
#pragma unroll
                for (int e = 0; e < 4; ++e) acc[t][u][e] = 0.f;

        for (int c = 0; c < 8; ++c){
            // A register staging into buf c%3 PAH/PAL (+ fused z on nh==0); safe:
            // that buffer's PAH/PAL last readers (chunk c-3) finished before B(c-1).
            {
                unsigned char* smb = sm + (c % 3)*SS;
                const unsigned* qs = g_qpk + (size_t)(r0 + row)*CC + c*32 + e0;
#pragma unroll
                for (int g = 0; g < 2; ++g){
                    uint4 A = *(const uint4*)(qs + g*8);
                    uint4 B = *(const uint4*)(qs + g*8 + 4);
                    unsigned p[8] = {A.x,A.y,A.z,A.w,B.x,B.y,B.z,B.w};
                    uint4 h, l;
                    h.x=(p[0]&0xffffu)|(p[1]<<16); h.y=(p[2]&0xffffu)|(p[3]<<16);
                    h.z=(p[4]&0xffffu)|(p[5]<<16); h.w=(p[6]&0xffffu)|(p[7]<<16);
                    l.x=(p[0]>>16)|(p[1]&0xffff0000u); l.y=(p[2]>>16)|(p[3]&0xffff0000u);
                    l.z=(p[4]>>16)|(p[5]&0xffff0000u); l.w=(p[6]>>16)|(p[7]&0xffff0000u);
                    const unsigned og = swoff(row, c0 + g, sws);
                    *(uint4*)(smb + PAH + og) = h;
                    *(uint4*)(smb + PAL + og) = l;
                    if (nh == 0){
                        const float* kp = ks_s + c*32 + e0 + g*8;
#pragma unroll
                        for (int u2 = 0; u2 < 8; ++u2) zacc += pkval(p[u2]) * kp[u2];
                    }
                }
            }
            if (c < 7){
                issueB(nh, c + 1, (c + 1) % 3);
                cpwaitg<1>();
                __syncthreads();
            } else {
                cpwaitg<0>();
                __syncthreads();      // ALL warps done chunk_mma(6) -> buf0 free
                if (nh == 0) issueB(1, 0, 0);   // prefetch nh=1 chunk0 into buf0
            }
            chunk_mma(sb + (unsigned)((c % 3)*SS), wm, wn, lane, sw, acc);
        }
        if (nh == 0){
            float s = zacc + __shfl_xor_sync(0xFFFFFFFFu, zacc, 1);
            if (!(tid & 1)) z_s[row] = 1.f / fmaxf(s, 1e-6f);
        }
        __syncthreads();   // z_s visible; all chunk_mma(7) done before nh=1 stages buf0 PAH

#pragma unroll
        for (int t = 0; t < 2; ++t){
            const int m = wm*32 + 16*t + (lane >> 2);
            const float z0 = z_s[m], z1 = z_s[m + 8];
#pragma unroll
            for (int u = 0; u < 8; ++u){
                const int ng = nh*128 + wn*64 + u*8 + 2*(lane & 3);
                float2 o;
                o.x = acc[t][u][0]*z0 + bo_s[ng];
                o.y = acc[t][u][1]*z0 + bo_s[ng + 1];
                *(float2*)(out + (size_t)(r0 + m)*CC + ng) = o;
                o.x = acc[t][u][2]*z1 + bo_s[ng];
                o.y = acc[t][u][3]*z1 + bo_s[ng + 1];
                *(float2*)(out + (size_t)(r0 + m + 8)*CC + ng) = o;
            }
        }
    }
}

// ------------------------- launch -------------------------
extern "C" void kernel_launch(void* const* d_in, const int* in_sizes, int n_in,
                              void* d_out, int out_size)
{
    (void)in_sizes; (void)n_in; (void)out_size;
    const float* x  = (const float*)d_in[0];
    const float* Wq = (const float*)d_in[1];
    const float* Wk = (const float*)d_in[2];
    const float* Wv = (const float*)d_in[3];
    const float* Wo = (const float*)d_in[4];
    const float* bo = (const float*)d_in[5];
    float* out = (float*)d_out;

    static int inited = 0;
    if (!inited){
        cudaFuncSetAttribute(qkv_mma, cudaFuncAttributeMaxDynamicSharedMemorySize, SMEM_DYN);
        cudaFuncSetAttribute(kv_mma,  cudaFuncAttributeMaxDynamicSharedMemorySize, SMEM_DYN);
        cudaFuncSetAttribute(out_mma, cudaFuncAttributeMaxDynamicSharedMemorySize, SMEM_DYN);
        inited = 1;
    }

    zero_kernel<<<256, 256>>>();
    presplit_x<<<32768, 256>>>(x);
    presplit_w<<<192, 256>>>(Wq, Wk, Wv);
    qkv_mma<<<NN/128, 256, SMEM_DYN>>>();
    kv_mma<<<dim3(2, 2, 74), 256, SMEM_DYN>>>();
    m_kernel<<<256, 256>>>(Wo);
    out_mma<<<NN/128, 256, SMEM_DYN>>>(bo, out);
}